// round 6
// baseline (speedup 1.0000x reference)
#include <cuda_runtime.h>
#include <cstdint>

#define Bdim 2
#define Lq 2048
#define Hdim 1024
#define NH 16
#define HD 64
#define MROWS (Bdim * Lq)   // 4096

// ---------------- scratch (static device arrays; no allocation) --------------
__device__ float g_Q[(size_t)Bdim * NH * Lq * HD];   // [b,h,l,d]
__device__ float g_K[(size_t)Bdim * NH * Lq * HD];
__device__ float g_V[(size_t)Bdim * NH * Lq * HD];
__device__ float g_ATT[(size_t)MROWS * Hdim];        // [b*l, h*64+d]
__device__ float g_O[(size_t)MROWS * Hdim];          // pre-LN projection

// ---------------- mma.sync helpers (baseline PTX, works on sm_103) -----------
__device__ __forceinline__ uint32_t f2tf32(float x) {
    uint32_t r;
    asm("cvt.rna.tf32.f32 %0, %1;" : "=r"(r) : "f"(x));
    return r;
}
__device__ __forceinline__ void split_tf32(float v, uint32_t& hi, uint32_t& lo) {
    hi = f2tf32(v);
    lo = f2tf32(v - __uint_as_float(hi));
}
// D = A(16x8) * B(8x8) + D, tf32 inputs, f32 accum
__device__ __forceinline__ void mma8(float* c, const uint32_t* a, const uint32_t* b) {
    asm volatile(
        "mma.sync.aligned.m16n8k8.row.col.f32.tf32.tf32.f32 "
        "{%0,%1,%2,%3}, {%4,%5,%6,%7}, {%8,%9}, {%0,%1,%2,%3};\n"
        : "+f"(c[0]), "+f"(c[1]), "+f"(c[2]), "+f"(c[3])
        : "r"(a[0]), "r"(a[1]), "r"(a[2]), "r"(a[3]), "r"(b[0]), "r"(b[1]));
}
__device__ __forceinline__ void lds4(uint32_t* r, const float* p) {
    uint4 v = *(const uint4*)p;
    r[0] = v.x; r[1] = v.y; r[2] = v.z; r[3] = v.w;
}
__device__ __forceinline__ void lds2(uint32_t* r, const float* p) {
    uint2 v = *(const uint2*)p;
    r[0] = v.x; r[1] = v.y;
}

// ============ GEMM: [4096x1024] @ [1024x1024] + bias, 3xTF32 =================
// Block 128x128, BK=32, 8 warps (4 in m x 2 in n), warp tile 32x64.
// Fragment-major smem: A-frag AF(mt0..7, kt0..3, lane, reg0..3),
//                      B-frag BF(nt0..15, kt0..3, lane, reg0..1), hi+lo planes.
// Buffer layout (floats): [Ah 4096][Al 4096][Bh 4096][Bl 4096] x 2 buffers.
#define GEMM_BUF_FLOATS 16384
#define GEMM_SMEM_BYTES (2 * GEMM_BUF_FLOATS * 4)
#define NKT 32   // 1024 / 32

__global__ __launch_bounds__(256) void gemm_tc(const float* __restrict__ Ag,
                                               const float* __restrict__ W,
                                               const float* __restrict__ bias,
                                               int which)
{
    extern __shared__ float sm[];
    const float* __restrict__ Ap = (which == 3) ? g_ATT : Ag;
    float* dst;
    if (which == 0) dst = g_Q;
    else if (which == 1) dst = g_K;
    else if (which == 2) dst = g_V;
    else dst = g_O;

    const int tid = threadIdx.x;
    const int wid = tid >> 5, lane = tid & 31;
    const int g = lane >> 2, t = lane & 3;
    const int wm = wid & 3, wn = wid >> 2;
    const int row0 = blockIdx.y * 128;
    const int col0 = blockIdx.x * 128;

    float acc[2][8][4];
#pragma unroll
    for (int i = 0; i < 2; i++)
#pragma unroll
        for (int j = 0; j < 8; j++)
#pragma unroll
            for (int r = 0; r < 4; r++) acc[i][j][r] = 0.f;

    float4 ra[4], rb[4];

    // ---- tile loaders / storers ----
    auto load_tile = [&](int kt) {
#pragma unroll
        for (int i = 0; i < 4; i++) {
            int e = tid + i * 256;          // 1024 float4: A 128 rows x 8 f4
            int m = e >> 3, k4 = (e & 7) * 4;
            ra[i] = *(const float4*)(Ap + (size_t)(row0 + m) * Hdim + kt * 32 + k4);
        }
#pragma unroll
        for (int i = 0; i < 4; i++) {
            int e = tid + i * 256;          // B: 32 rows x 32 f4
            int kr = e >> 5, n4 = (e & 31) * 4;
            rb[i] = *(const float4*)(W + (size_t)(kt * 32 + kr) * Hdim + col0 + n4);
        }
    };
    auto store_tile = [&](int s) {
        float* Ah = sm + s * GEMM_BUF_FLOATS;
        float* Al = Ah + 4096;
        float* Bh = Ah + 8192;
        float* Bl = Ah + 12288;
#pragma unroll
        for (int i = 0; i < 4; i++) {
            int e = tid + i * 256;
            int m = e >> 3, k4 = (e & 7) * 4;
            int mt = m >> 4, lm = m & 15;
            int kt8 = k4 >> 3, rbit = (k4 >> 2) & 1;
            int reg = (lm >> 3) + 2 * rbit;
            int off0 = (((mt * 4 + kt8) * 32) + (lm & 7) * 4) * 4 + reg;
            float vv[4] = {ra[i].x, ra[i].y, ra[i].z, ra[i].w};
#pragma unroll
            for (int j = 0; j < 4; j++) {
                uint32_t hi, lo; split_tf32(vv[j], hi, lo);
                Ah[off0 + 4 * j] = __uint_as_float(hi);
                Al[off0 + 4 * j] = __uint_as_float(lo);
            }
        }
#pragma unroll
        for (int i = 0; i < 4; i++) {
            int e = tid + i * 256;
            int kr = e >> 5, n4 = (e & 31) * 4;
            int kt8 = kr >> 3, kk = kr & 7;
            int tt = kk & 3, rr = kk >> 2;
            int nt = n4 >> 3, g0 = n4 & 7;
            float vv[4] = {rb[i].x, rb[i].y, rb[i].z, rb[i].w};
#pragma unroll
            for (int j = 0; j < 4; j++) {
                int off = (((nt * 4 + kt8) * 32) + (g0 + j) * 4 + tt) * 2 + rr;
                uint32_t hi, lo; split_tf32(vv[j], hi, lo);
                Bh[off] = __uint_as_float(hi);
                Bl[off] = __uint_as_float(lo);
            }
        }
    };

    load_tile(0);
    store_tile(0);
    __syncthreads();

    for (int kt = 0; kt < NKT; kt++) {
        const int s = kt & 1;
        if (kt + 1 < NKT) load_tile(kt + 1);

        const float* Ah = sm + s * GEMM_BUF_FLOATS;
        const float* Al = Ah + 4096;
        const float* Bh = Ah + 8192;
        const float* Bl = Ah + 12288;

#pragma unroll
        for (int k8 = 0; k8 < 4; k8++) {
            uint32_t ah[2][4], al[2][4];
#pragma unroll
            for (int mt = 0; mt < 2; mt++) {
                int off = (((wm * 2 + mt) * 4 + k8) * 32 + lane) * 4;
                lds4(ah[mt], Ah + off);
                lds4(al[mt], Al + off);
            }
#pragma unroll
            for (int nt = 0; nt < 8; nt++) {
                uint32_t bh[2], bl[2];
                int off = (((wn * 8 + nt) * 4 + k8) * 32 + lane) * 2;
                lds2(bh, Bh + off);
                lds2(bl, Bl + off);
#pragma unroll
                for (int mt = 0; mt < 2; mt++) {
                    mma8(acc[mt][nt], ah[mt], bh);
                    mma8(acc[mt][nt], ah[mt], bl);
                    mma8(acc[mt][nt], al[mt], bh);
                }
            }
        }
        __syncthreads();
        if (kt + 1 < NKT) { store_tile(s ^ 1); __syncthreads(); }
    }

    // epilogue: bias + scatter (head-split for QKV, row-major for O-proj)
#pragma unroll
    for (int mt = 0; mt < 2; mt++)
#pragma unroll
        for (int nt = 0; nt < 8; nt++)
#pragma unroll
            for (int r = 0; r < 4; r++) {
                int row = row0 + wm * 32 + mt * 16 + g + (r >> 1) * 8;
                int col = col0 + wn * 64 + nt * 8 + t * 2 + (r & 1);
                float v = acc[mt][nt][r] + bias[col];
                if (which < 3) {
                    int bb = row >> 11, l = row & (Lq - 1);
                    int h = col >> 6, d = col & 63;
                    dst[(((size_t)(bb * NH + h)) * Lq + l) * HD + d] = v;
                } else {
                    dst[(size_t)row * Hdim + col] = v;
                }
            }
}

// ============ Flash attention with mma (keys = V, values = K) ================
// energies = Q @ V^T / 4 + mask; attended = softmax(energies) @ K
// Block: 128 q-rows, 8 warps x 16 rows. KB=64. 3xTF32 for S, tf32 for PV.
// smem (floats): Qh 0(8192) Ql 8192 Ksh 16384(4096) Ksl 20480 Vs 24576(4096)
//                Ps 28672(8192) msk 36864(64)  => 147,712 B
#define ATTN_SMEM_BYTES (36928 * 4)

__global__ __launch_bounds__(256) void attn_k(const float* __restrict__ mask)
{
    extern __shared__ float sm[];
    float* Qh  = sm;
    float* Ql  = sm + 8192;
    float* Ksh = sm + 16384;
    float* Ksl = sm + 20480;
    float* Vs  = sm + 24576;
    float* Ps  = sm + 28672;
    float* msk = sm + 36864;

    const int tid = threadIdx.x;
    const int wid = tid >> 5, lane = tid & 31;
    const int g = lane >> 2, t = lane & 3;
    const int q0 = blockIdx.x * 128;
    const int h  = blockIdx.y;
    const int b  = blockIdx.z;
    const size_t bh = (size_t)(b * NH + h);
    const float* __restrict__ Qg = g_Q + bh * Lq * HD;
    const float* __restrict__ Kg = g_V + bh * Lq * HD;   // keys are V
    const float* __restrict__ Vg = g_K + bh * Lq * HD;   // values are K

    // ---- stage Q once (A-frag layout, hi/lo) ----
#pragma unroll
    for (int i = 0; i < 8; i++) {
        int e = tid + i * 256;               // 2048 f4 = 128 rows x 16 f4
        int m = e >> 4, d4 = (e & 15) * 4;
        float4 v = *(const float4*)(Qg + (size_t)(q0 + m) * HD + d4);
        int mt = m >> 4, lm = m & 15;
        int kt = d4 >> 3, rbit = (d4 >> 2) & 1;
        int reg = (lm >> 3) + 2 * rbit;
        int off0 = (((mt * 8 + kt) * 32) + (lm & 7) * 4) * 4 + reg;
        float vv[4] = {v.x, v.y, v.z, v.w};
#pragma unroll
        for (int j = 0; j < 4; j++) {
            uint32_t hi, lo; split_tf32(vv[j], hi, lo);
            Qh[off0 + 4 * j] = __uint_as_float(hi);
            Ql[off0 + 4 * j] = __uint_as_float(lo);
        }
    }

    float mprev[2] = {-1e30f, -1e30f};
    float lsum[2]  = {0.f, 0.f};
    float accO[8][4];
#pragma unroll
    for (int nt = 0; nt < 8; nt++)
#pragma unroll
        for (int r = 0; r < 4; r++) accO[nt][r] = 0.f;

    for (int kb = 0; kb < Lq / 64; kb++) {
        const int k0 = kb * 64;
        __syncthreads();                       // prev iter PV done
        // stage Ks (B-frag for S: k = d, n = key), hi/lo
#pragma unroll
        for (int i = 0; i < 4; i++) {
            int e = tid + i * 256;             // 1024 f4 = 64 keys x 16 f4
            int key = e >> 4, d4 = (e & 15) * 4;
            float4 v = *(const float4*)(Kg + (size_t)(k0 + key) * HD + d4);
            int nt = key >> 3, gk = key & 7;
            int kt = d4 >> 3, rr = (d4 >> 2) & 1;
            float vv[4] = {v.x, v.y, v.z, v.w};
#pragma unroll
            for (int j = 0; j < 4; j++) {
                int tt = (d4 + j) & 3;
                int off = (((nt * 8 + kt) * 32) + gk * 4 + tt) * 2 + rr;
                uint32_t hi, lo; split_tf32(vv[j], hi, lo);
                Ksh[off] = __uint_as_float(hi);
                Ksl[off] = __uint_as_float(lo);
            }
        }
        // stage Vs (B-frag for PV: k = key, n = d), single tf32
#pragma unroll
        for (int i = 0; i < 4; i++) {
            int e = tid + i * 256;
            int key = e >> 4, d4 = (e & 15) * 4;
            float4 v = *(const float4*)(Vg + (size_t)(k0 + key) * HD + d4);
            int kt = key >> 3, kk = key & 7;
            int tt = kk & 3, rr = kk >> 2;
            int nt = d4 >> 3, g0 = d4 & 7;
            float vv[4] = {v.x, v.y, v.z, v.w};
#pragma unroll
            for (int j = 0; j < 4; j++) {
                int off = (((nt * 8 + kt) * 32) + (g0 + j) * 4 + tt) * 2 + rr;
                Vs[off] = __uint_as_float(f2tf32(vv[j]));
            }
        }
        if (tid < 64) msk[tid] = mask[b * Lq + k0 + tid];
        __syncthreads();

        // ---- S = Q @ keys^T (3xTF32) ----
        float accS[8][4];
#pragma unroll
        for (int nt = 0; nt < 8; nt++)
#pragma unroll
            for (int r = 0; r < 4; r++) accS[nt][r] = 0.f;
#pragma unroll
        for (int kt = 0; kt < 8; kt++) {
            uint32_t ah[4], al[4];
            int aoff = (((wid * 8 + kt) * 32) + lane) * 4;
            lds4(ah, Qh + aoff);
            lds4(al, Ql + aoff);
#pragma unroll
            for (int nt = 0; nt < 8; nt++) {
                uint32_t bhf[2], blf[2];
                int boff = (((nt * 8 + kt) * 32) + lane) * 2;
                lds2(bhf, Ksh + boff);
                lds2(blf, Ksl + boff);
                mma8(accS[nt], ah, bhf);
                mma8(accS[nt], ah, blf);
                mma8(accS[nt], al, bhf);
            }
        }
        // scale + mask
#pragma unroll
        for (int nt = 0; nt < 8; nt++)
#pragma unroll
            for (int r = 0; r < 4; r++)
                accS[nt][r] = accS[nt][r] * 0.25f + msk[nt * 8 + 2 * t + (r & 1)];

        // ---- online softmax (rows g and g+8), quad-reduce over lanes ----
        float mx[2] = {-1e30f, -1e30f};
#pragma unroll
        for (int nt = 0; nt < 8; nt++) {
            mx[0] = fmaxf(mx[0], fmaxf(accS[nt][0], accS[nt][1]));
            mx[1] = fmaxf(mx[1], fmaxf(accS[nt][2], accS[nt][3]));
        }
#pragma unroll
        for (int o = 1; o <= 2; o <<= 1) {
            mx[0] = fmaxf(mx[0], __shfl_xor_sync(0xffffffffu, mx[0], o));
            mx[1] = fmaxf(mx[1], __shfl_xor_sync(0xffffffffu, mx[1], o));
        }
        float fct[2], mnew[2], rsum[2] = {0.f, 0.f};
#pragma unroll
        for (int r2 = 0; r2 < 2; r2++) {
            mnew[r2] = fmaxf(mprev[r2], mx[r2]);
            fct[r2]  = __expf(mprev[r2] - mnew[r2]);
            mprev[r2] = mnew[r2];
        }
#pragma unroll
        for (int nt = 0; nt < 8; nt++)
#pragma unroll
            for (int r = 0; r < 4; r++) {
                int r2 = r >> 1;
                float p = __expf(accS[nt][r] - mnew[r2]);
                accS[nt][r] = p;
                rsum[r2] += p;
            }
#pragma unroll
        for (int o = 1; o <= 2; o <<= 1) {
            rsum[0] += __shfl_xor_sync(0xffffffffu, rsum[0], o);
            rsum[1] += __shfl_xor_sync(0xffffffffu, rsum[1], o);
        }
        lsum[0] = lsum[0] * fct[0] + rsum[0];
        lsum[1] = lsum[1] * fct[1] + rsum[1];
#pragma unroll
        for (int nt = 0; nt < 8; nt++)
#pragma unroll
            for (int r = 0; r < 4; r++) accO[nt][r] *= fct[r >> 1];

        // ---- store P in A-frag layout (tf32) ----
#pragma unroll
        for (int nt = 0; nt < 8; nt++)
#pragma unroll
            for (int r = 0; r < 4; r++) {
                int x = nt * 8 + 2 * t + (r & 1);          // key col
                int lanep = g * 4 + (x & 3);
                int regp = (r >> 1) + 2 * ((x >> 2) & 1);
                int off = (((wid * 8 + nt) * 32) + lanep) * 4 + regp;
                Ps[off] = __uint_as_float(f2tf32(accS[nt][r]));
            }
        __syncthreads();

        // ---- O += P @ values ----
#pragma unroll
        for (int kt = 0; kt < 8; kt++) {
            uint32_t ap[4];
            lds4(ap, Ps + (((wid * 8 + kt) * 32) + lane) * 4);
#pragma unroll
            for (int nt = 0; nt < 8; nt++) {
                uint32_t bv[2];
                lds2(bv, Vs + (((nt * 8 + kt) * 32) + lane) * 2);
                mma8(accO[nt], ap, bv);
            }
        }
    }

    const float inv[2] = {1.0f / lsum[0], 1.0f / lsum[1]};
#pragma unroll
    for (int nt = 0; nt < 8; nt++)
#pragma unroll
        for (int r = 0; r < 4; r++) {
            int q = q0 + wid * 16 + g + (r >> 1) * 8;
            int col = nt * 8 + 2 * t + (r & 1);
            g_ATT[((size_t)(b * Lq + q)) * Hdim + h * HD + col] =
                accO[nt][r] * inv[r >> 1];
        }
}

// ---------------- residual + LayerNorm ---------------------------------------
__global__ __launch_bounds__(256) void ln_k(const float* __restrict__ X,
                                            const float* __restrict__ gamma,
                                            const float* __restrict__ beta,
                                            float* __restrict__ out)
{
    __shared__ float buf[Hdim];
    __shared__ float rs[8], rss[8], stats[2];
    const int m = blockIdx.x;
    const int tid = threadIdx.x;
    const int lane = tid & 31, wid = tid >> 5;

    float s = 0.f, ss = 0.f;
#pragma unroll
    for (int i = 0; i < 4; i++) {
        int hh = i * 256 + tid;
        float v = g_O[(size_t)m * Hdim + hh] + X[(size_t)m * Hdim + hh];
        buf[hh] = v;
        s += v; ss += v * v;
    }
#pragma unroll
    for (int o = 16; o > 0; o >>= 1) {
        s  += __shfl_xor_sync(0xffffffffu, s, o);
        ss += __shfl_xor_sync(0xffffffffu, ss, o);
    }
    if (lane == 0) { rs[wid] = s; rss[wid] = ss; }
    __syncthreads();
    if (tid == 0) {
        float S = 0.f, SS = 0.f;
#pragma unroll
        for (int i = 0; i < 8; i++) { S += rs[i]; SS += rss[i]; }
        float mu = S * (1.0f / Hdim);
        stats[0] = mu;
        stats[1] = rsqrtf(SS * (1.0f / Hdim) - mu * mu + 1e-12f);
    }
    __syncthreads();
    float mu = stats[0], r = stats[1];
#pragma unroll
    for (int i = 0; i < 4; i++) {
        int hh = i * 256 + tid;
        out[(size_t)m * Hdim + hh] = (buf[hh] - mu) * r * gamma[hh] + beta[hh];
    }
}

// ---------------- launch ------------------------------------------------------
extern "C" void kernel_launch(void* const* d_in, const int* in_sizes, int n_in,
                              void* d_out, int out_size)
{
    const float* X     = (const float*)d_in[0];
    const float* mask  = (const float*)d_in[1];
    const float* Wq    = (const float*)d_in[2];
    const float* bq    = (const float*)d_in[3];
    const float* Wk    = (const float*)d_in[4];
    const float* bk    = (const float*)d_in[5];
    const float* Wv    = (const float*)d_in[6];
    const float* bv    = (const float*)d_in[7];
    const float* Wo    = (const float*)d_in[8];
    const float* bo    = (const float*)d_in[9];
    const float* gamma = (const float*)d_in[10];
    const float* beta  = (const float*)d_in[11];

    cudaFuncSetAttribute(gemm_tc, cudaFuncAttributeMaxDynamicSharedMemorySize,
                         GEMM_SMEM_BYTES);
    cudaFuncSetAttribute(attn_k, cudaFuncAttributeMaxDynamicSharedMemorySize,
                         ATTN_SMEM_BYTES);

    dim3 gg(Hdim / 128, MROWS / 128);   // (8, 32)
    gemm_tc<<<gg, 256, GEMM_SMEM_BYTES>>>(X, Wq, bq, 0);
    gemm_tc<<<gg, 256, GEMM_SMEM_BYTES>>>(X, Wk, bk, 1);
    gemm_tc<<<gg, 256, GEMM_SMEM_BYTES>>>(X, Wv, bv, 2);

    attn_k<<<dim3(Lq / 128, NH, Bdim), 256, ATTN_SMEM_BYTES>>>(mask);

    gemm_tc<<<gg, 256, GEMM_SMEM_BYTES>>>(nullptr, Wo, bo, 3);

    ln_k<<<MROWS, 256>>>(X, gamma, beta, (float*)d_out);
}

// round 8
// speedup vs baseline: 4.5120x; 4.5120x over previous
#include <cuda_runtime.h>
#include <cuda_bf16.h>
#include <cstdint>

#define Bdim 2
#define Lq 2048
#define Hdim 1024
#define NH 16
#define HD 64
#define MROWS (Bdim * Lq)   // 4096
#define HH (Hdim * Hdim)

// ---------------- scratch (static device arrays; no allocation) --------------
__device__ __nv_bfloat16 g_Xh[(size_t)MROWS * Hdim];
__device__ __nv_bfloat16 g_Xl[(size_t)MROWS * Hdim];
__device__ __nv_bfloat16 g_Wh[(size_t)4 * HH];     // transposed [n][k], slots Wq,Wk,Wv,Wo
__device__ __nv_bfloat16 g_Wl[(size_t)4 * HH];
__device__ __nv_bfloat16 g_Qh[(size_t)MROWS * Hdim];   // [bh][l][d]
__device__ __nv_bfloat16 g_Ql[(size_t)MROWS * Hdim];
__device__ __nv_bfloat16 g_Kh[(size_t)MROWS * Hdim];   // keys (= V-proj), [bh][l][d]
__device__ __nv_bfloat16 g_Kl[(size_t)MROWS * Hdim];
__device__ float         g_Vt[(size_t)MROWS * Hdim];   // values (= K-proj), [bh][d][l], tf32
__device__ __nv_bfloat16 g_ATTh[(size_t)MROWS * Hdim]; // [b*l][h*64+d]
__device__ __nv_bfloat16 g_ATTl[(size_t)MROWS * Hdim];
__device__ float         g_O[(size_t)MROWS * Hdim];

// ---------------- PTX helpers -------------------------------------------------
__device__ __forceinline__ uint32_t smem_u32(const void* p) {
    uint32_t a;
    asm("{ .reg .u64 t; cvta.to.shared.u64 t, %1; cvt.u32.u64 %0, t; }"
        : "=r"(a) : "l"(p));
    return a;
}
__device__ __forceinline__ void cpa16(uint32_t s, const void* g) {
    asm volatile("cp.async.cg.shared.global [%0], [%1], 16;" :: "r"(s), "l"(g));
}
#define CP_COMMIT() asm volatile("cp.async.commit_group;" ::: "memory")
#define CP_WAIT(n)  asm volatile("cp.async.wait_group %0;" :: "n"(n) : "memory")

__device__ __forceinline__ void ldsm4(uint32_t* r, uint32_t a) {
    asm volatile("ldmatrix.sync.aligned.m8n8.x4.shared.b16 {%0,%1,%2,%3}, [%4];"
                 : "=r"(r[0]), "=r"(r[1]), "=r"(r[2]), "=r"(r[3]) : "r"(a));
}
__device__ __forceinline__ void mma_bf16(float* c, const uint32_t* a, const uint32_t* b) {
    asm volatile(
        "mma.sync.aligned.m16n8k16.row.col.f32.bf16.bf16.f32 "
        "{%0,%1,%2,%3}, {%4,%5,%6,%7}, {%8,%9}, {%0,%1,%2,%3};\n"
        : "+f"(c[0]), "+f"(c[1]), "+f"(c[2]), "+f"(c[3])
        : "r"(a[0]), "r"(a[1]), "r"(a[2]), "r"(a[3]), "r"(b[0]), "r"(b[1]));
}
__device__ __forceinline__ void mma_tf32(float* c, const uint32_t* a, const uint32_t* b) {
    asm volatile(
        "mma.sync.aligned.m16n8k8.row.col.f32.tf32.tf32.f32 "
        "{%0,%1,%2,%3}, {%4,%5,%6,%7}, {%8,%9}, {%0,%1,%2,%3};\n"
        : "+f"(c[0]), "+f"(c[1]), "+f"(c[2]), "+f"(c[3])
        : "r"(a[0]), "r"(a[1]), "r"(a[2]), "r"(a[3]), "r"(b[0]), "r"(b[1]));
}
__device__ __forceinline__ uint32_t f2tf32(float x) {
    uint32_t r;
    asm("cvt.rna.tf32.f32 %0, %1;" : "=r"(r) : "f"(x));
    return r;
}
__device__ __forceinline__ float ex2(float x) {
    float y;
    asm("ex2.approx.f32 %0, %1;" : "=f"(y) : "f"(x));
    return y;
}
__device__ __forceinline__ void split_store2(__nv_bfloat16* ph, __nv_bfloat16* pl,
                                             float v0, float v1) {
    __nv_bfloat162 h, l;
    h.x = __float2bfloat16(v0); l.x = __float2bfloat16(v0 - __bfloat162float(h.x));
    h.y = __float2bfloat16(v1); l.y = __float2bfloat16(v1 - __bfloat162float(h.y));
    *(__nv_bfloat162*)ph = h;
    *(__nv_bfloat162*)pl = l;
}

// ---------------- preprocessing: split X, transpose+split W -------------------
__global__ __launch_bounds__(256) void split_x(const float* __restrict__ x) {
    int e = (blockIdx.x * 256 + threadIdx.x) * 4;
    float4 v = *(const float4*)(x + e);
    __nv_bfloat162 h0, l0, h1, l1;
    h0.x = __float2bfloat16(v.x); l0.x = __float2bfloat16(v.x - __bfloat162float(h0.x));
    h0.y = __float2bfloat16(v.y); l0.y = __float2bfloat16(v.y - __bfloat162float(h0.y));
    h1.x = __float2bfloat16(v.z); l1.x = __float2bfloat16(v.z - __bfloat162float(h1.x));
    h1.y = __float2bfloat16(v.w); l1.y = __float2bfloat16(v.w - __bfloat162float(h1.y));
    *(__nv_bfloat162*)(g_Xh + e)     = h0;
    *(__nv_bfloat162*)(g_Xl + e)     = l0;
    *(__nv_bfloat162*)(g_Xh + e + 2) = h1;
    *(__nv_bfloat162*)(g_Xl + e + 2) = l1;
}

__global__ __launch_bounds__(256) void split_w(const float* __restrict__ W0,
                                               const float* __restrict__ W1,
                                               const float* __restrict__ W2,
                                               const float* __restrict__ W3) {
    __shared__ float tb[32][33];
    const int w = blockIdx.z;
    const float* src = (w == 0) ? W0 : (w == 1) ? W1 : (w == 2) ? W2 : W3;
    const int k0 = blockIdx.x * 32, n0 = blockIdx.y * 32;
    const int tx = threadIdx.x & 31, ty = threadIdx.x >> 5;  // 32 x 8
#pragma unroll
    for (int i = 0; i < 4; i++) {
        int r = ty + i * 8;
        tb[r][tx] = src[(size_t)(k0 + r) * Hdim + n0 + tx];   // read [k][n]
    }
    __syncthreads();
    __nv_bfloat16* dh = g_Wh + (size_t)w * HH;
    __nv_bfloat16* dl = g_Wl + (size_t)w * HH;
#pragma unroll
    for (int i = 0; i < 4; i++) {
        int r = ty + i * 8;                                  // output n = n0+r, k = k0+tx
        float v = tb[tx][r];
        __nv_bfloat16 h = __float2bfloat16(v);
        __nv_bfloat16 l = __float2bfloat16(v - __bfloat162float(h));
        dh[(size_t)(n0 + r) * Hdim + k0 + tx] = h;
        dl[(size_t)(n0 + r) * Hdim + k0 + tx] = l;
    }
}

// ============ GEMM: 128x128x(BK=32) bf16 3-plane + epilogue router ============
// smem per buffer: Ah 8K | Al 8K | Bh 8K | Bl 8K = 32KB; 2 buffers = 64KB
#define GEMM_SMEM_BYTES (64 * 1024)
#define NKT 32

__global__ __launch_bounds__(256) void gemm_tc(const float* __restrict__ bias, int which)
{
    extern __shared__ char smc[];
    const uint32_t sb = smem_u32(smc);
    const int tid = threadIdx.x;
    const int wid = tid >> 5, lane = tid & 31;
    const int g = lane >> 2, t = lane & 3;
    const int wm = wid & 3, wn = wid >> 2;            // 4x2 warps, tile 32m x 64n
    const int row0 = blockIdx.y * 128, col0 = blockIdx.x * 128;

    const __nv_bfloat16* __restrict__ Ah_g = (which == 3) ? g_ATTh : g_Xh;
    const __nv_bfloat16* __restrict__ Al_g = (which == 3) ? g_ATTl : g_Xl;
    const __nv_bfloat16* __restrict__ Bh_g = g_Wh + (size_t)which * HH;
    const __nv_bfloat16* __restrict__ Bl_g = g_Wl + (size_t)which * HH;

    float acc[2][8][4];
#pragma unroll
    for (int i = 0; i < 2; i++)
#pragma unroll
        for (int j = 0; j < 8; j++)
#pragma unroll
            for (int r = 0; r < 4; r++) acc[i][j][r] = 0.f;

    auto stage = [&](int kt, int s) {
        const uint32_t ab = sb + s * 32768;
#pragma unroll
        for (int i = 0; i < 2; i++) {
            int e = tid + i * 256;
            int m = e >> 2, c = e & 3;
            uint32_t off = m * 64 + ((c ^ ((m >> 1) & 3)) << 4);
            size_t ga = (size_t)(row0 + m) * Hdim + kt * 32 + c * 8;
            cpa16(ab + off,         Ah_g + ga);
            cpa16(ab + 8192 + off,  Al_g + ga);
            size_t gb = (size_t)(col0 + m) * Hdim + kt * 32 + c * 8;
            cpa16(ab + 16384 + off, Bh_g + gb);
            cpa16(ab + 24576 + off, Bl_g + gb);
        }
        CP_COMMIT();
    };

    stage(0, 0);
    for (int kt = 0; kt < NKT; kt++) {
        const int s = kt & 1;
        if (kt + 1 < NKT) { stage(kt + 1, s ^ 1); CP_WAIT(1); }
        else              { CP_WAIT(0); }
        __syncthreads();
        const uint32_t ab = sb + s * 32768;
#pragma unroll
        for (int kc = 0; kc < 2; kc++) {
            uint32_t ah[2][4], al[2][4];
#pragma unroll
            for (int mt = 0; mt < 2; mt++) {
                int m = wm * 32 + mt * 16 + (lane & 7) + ((lane >> 3) & 1) * 8;
                int c = kc * 2 + (lane >> 4);
                uint32_t off = m * 64 + ((c ^ ((m >> 1) & 3)) << 4);
                ldsm4(ah[mt], ab + off);
                ldsm4(al[mt], ab + 8192 + off);
            }
            uint32_t bhf[4][4], blf[4][4];
#pragma unroll
            for (int p = 0; p < 4; p++) {
                int q = lane >> 3;
                int n = wn * 64 + p * 16 + (lane & 7) + ((q >> 1) << 3);
                int c = kc * 2 + (q & 1);
                uint32_t off = n * 64 + ((c ^ ((n >> 1) & 3)) << 4);
                ldsm4(bhf[p], ab + 16384 + off);
                ldsm4(blf[p], ab + 24576 + off);
            }
#pragma unroll
            for (int nt = 0; nt < 8; nt++) {
                const uint32_t* bh_ = &bhf[nt >> 1][(nt & 1) * 2];
                const uint32_t* bl_ = &blf[nt >> 1][(nt & 1) * 2];
#pragma unroll
                for (int mt = 0; mt < 2; mt++) {
                    mma_bf16(acc[mt][nt], ah[mt], bh_);
                    mma_bf16(acc[mt][nt], ah[mt], bl_);
                    mma_bf16(acc[mt][nt], al[mt], bh_);
                }
            }
        }
        __syncthreads();
    }

    // epilogue: bias + route to next-stage format
#pragma unroll
    for (int mt = 0; mt < 2; mt++)
#pragma unroll
        for (int nt = 0; nt < 8; nt++) {
            int colb = col0 + wn * 64 + nt * 8 + 2 * t;
            float b0 = bias[colb], b1 = bias[colb + 1];
#pragma unroll
            for (int rp = 0; rp < 2; rp++) {
                int row = row0 + wm * 32 + mt * 16 + g + rp * 8;
                float v0 = acc[mt][nt][rp * 2 + 0] + b0;
                float v1 = acc[mt][nt][rp * 2 + 1] + b1;
                int bb = row >> 11, l = row & (Lq - 1);
                int h = colb >> 6, d = colb & 63;
                if (which == 0) {
                    size_t o = (((size_t)(bb * NH + h)) * Lq + l) * HD + d;
                    split_store2(g_Qh + o, g_Ql + o, v0, v1);
                } else if (which == 2) {
                    size_t o = (((size_t)(bb * NH + h)) * Lq + l) * HD + d;
                    split_store2(g_Kh + o, g_Kl + o, v0, v1);
                } else if (which == 1) {
                    size_t o = ((size_t)(bb * NH + h) * HD + d) * Lq + l;
                    g_Vt[o]      = __uint_as_float(f2tf32(v0));
                    g_Vt[o + Lq] = __uint_as_float(f2tf32(v1));
                } else {
                    float2 v; v.x = v0; v.y = v1;
                    *(float2*)(g_O + (size_t)row * Hdim + colb) = v;
                }
            }
        }
}

// ============ Flash attention (keys = V-proj, values = K-proj) ================
// energies = Q @ keys^T / 4 + mask; attended = softmax @ values
// smem: QH 16K | QL 16K | 2x{ KH 8K | KL 8K | VS 16K } | 2x mask 256B = 98816 B
#define NKB (Lq / 64)
#define ATTN_SMEM_BYTES 98816

__global__ __launch_bounds__(256) void attn_k(const float* __restrict__ mask)
{
    extern __shared__ char smc[];
    const uint32_t sb = smem_u32(smc);
    const int tid = threadIdx.x;
    const int wid = tid >> 5, lane = tid & 31;
    const int g = lane >> 2, t = lane & 3;
    const int q0 = blockIdx.x * 128;
    const int h = blockIdx.y, b = blockIdx.z;
    const int bh = b * NH + h;
    const float* __restrict__ maskp = mask + (size_t)b * Lq;

    const float LOG2E = 1.4426950408889634f;
    const float C025  = 0.25f * LOG2E;

    // ---- stage Q (group 0) ----
#pragma unroll
    for (int i = 0; i < 4; i++) {
        int e = tid + i * 256;
        int q = e >> 3, c = e & 7;
        uint32_t off = q * 128 + ((c ^ (q & 7)) << 4);
        size_t ga = (size_t)((size_t)bh * Lq + q0 + q) * HD + c * 8;
        cpa16(sb + off,         g_Qh + ga);
        cpa16(sb + 16384 + off, g_Ql + ga);
    }
    CP_COMMIT();

    auto stageKV = [&](int kb, int s) {
        const int k0 = kb * 64;
        const uint32_t kvb = sb + 32768 + s * 32768;
#pragma unroll
        for (int i = 0; i < 2; i++) {
            int e = tid + i * 256;
            int key = e >> 3, c = e & 7;
            uint32_t off = key * 128 + ((c ^ (key & 7)) << 4);
            size_t ga = (size_t)((size_t)bh * Lq + k0 + key) * HD + c * 8;
            cpa16(kvb + off,        g_Kh + ga);
            cpa16(kvb + 8192 + off, g_Kl + ga);
        }
#pragma unroll
        for (int i = 0; i < 4; i++) {
            int e = tid + i * 256;
            int d = e >> 4, c = e & 15;
            uint32_t off = d * 256 + ((c ^ (d & 7)) << 4);
            cpa16(kvb + 16384 + off, g_Vt + ((size_t)bh * HD + d) * Lq + k0 + c * 4);
        }
        if (tid < 16) cpa16(sb + 98304 + s * 256 + tid * 16, maskp + k0 + tid * 4);
        CP_COMMIT();
    };

    stageKV(0, 0);

    float mprev[2] = {-1e30f, -1e30f};
    float lsum[2]  = {0.f, 0.f};
    float accO[8][4];
#pragma unroll
    for (int nt = 0; nt < 8; nt++)
#pragma unroll
        for (int r = 0; r < 4; r++) accO[nt][r] = 0.f;

    for (int kb = 0; kb < NKB; kb++) {
        const int s = kb & 1;
        if (kb + 1 < NKB) { stageKV(kb + 1, s ^ 1); CP_WAIT(1); }
        else              { CP_WAIT(0); }
        __syncthreads();
        const uint32_t kvb = sb + 32768 + s * 32768;

        // ---- S = Q @ keys^T (bf16 3-plane, k over d=64) ----
        float accS[8][4];
#pragma unroll
        for (int nt = 0; nt < 8; nt++)
#pragma unroll
            for (int r = 0; r < 4; r++) accS[nt][r] = 0.f;

#pragma unroll
        for (int kc = 0; kc < 4; kc++) {
            uint32_t qh[4], ql[4];
            {
                int m = wid * 16 + (lane & 7) + ((lane >> 3) & 1) * 8;
                int c = kc * 2 + (lane >> 4);
                uint32_t off = m * 128 + ((c ^ (m & 7)) << 4);
                ldsm4(qh, sb + off);
                ldsm4(ql, sb + 16384 + off);
            }
            uint32_t kh[4][4], kl[4][4];
#pragma unroll
            for (int p = 0; p < 4; p++) {
                int q = lane >> 3;
                int key = p * 16 + (lane & 7) + ((q >> 1) << 3);
                int c = kc * 2 + (q & 1);
                uint32_t off = key * 128 + ((c ^ (key & 7)) << 4);
                ldsm4(kh[p], kvb + off);
                ldsm4(kl[p], kvb + 8192 + off);
            }
#pragma unroll
            for (int nt = 0; nt < 8; nt++) {
                const uint32_t* bh_ = &kh[nt >> 1][(nt & 1) * 2];
                const uint32_t* bl_ = &kl[nt >> 1][(nt & 1) * 2];
                mma_bf16(accS[nt], qh, bh_);
                mma_bf16(accS[nt], qh, bl_);
                mma_bf16(accS[nt], ql, bh_);
            }
        }

        // ---- scale + mask (log2 domain) ----
        const float* ms = (const float*)(smc + 98304 + s * 256);
#pragma unroll
        for (int nt = 0; nt < 8; nt++) {
            float m0 = ms[nt * 8 + 2 * t]     * LOG2E;
            float m1 = ms[nt * 8 + 2 * t + 1] * LOG2E;
#pragma unroll
            for (int r = 0; r < 4; r++)
                accS[nt][r] = accS[nt][r] * C025 + ((r & 1) ? m1 : m0);
        }

        // ---- online softmax (rows g, g+8), quad reduce ----
        float mx[2] = {-1e30f, -1e30f};
#pragma unroll
        for (int nt = 0; nt < 8; nt++) {
            mx[0] = fmaxf(mx[0], fmaxf(accS[nt][0], accS[nt][1]));
            mx[1] = fmaxf(mx[1], fmaxf(accS[nt][2], accS[nt][3]));
        }
#pragma unroll
        for (int o = 1; o <= 2; o <<= 1) {
            mx[0] = fmaxf(mx[0], __shfl_xor_sync(0xffffffffu, mx[0], o));
            mx[1] = fmaxf(mx[1], __shfl_xor_sync(0xffffffffu, mx[1], o));
        }
        float fct[2], mnew[2], rsum[2] = {0.f, 0.f};
#pragma unroll
        for (int r2 = 0; r2 < 2; r2++) {
            mnew[r2] = fmaxf(mprev[r2], mx[r2]);
            fct[r2]  = ex2(mprev[r2] - mnew[r2]);
            mprev[r2] = mnew[r2];
        }
#pragma unroll
        for (int nt = 0; nt < 8; nt++)
#pragma unroll
            for (int r = 0; r < 4; r++) {
                float p = ex2(accS[nt][r] - mnew[r >> 1]);
                accS[nt][r] = p;
                rsum[r >> 1] += p;
            }
#pragma unroll
        for (int o = 1; o <= 2; o <<= 1) {
            rsum[0] += __shfl_xor_sync(0xffffffffu, rsum[0], o);
            rsum[1] += __shfl_xor_sync(0xffffffffu, rsum[1], o);
        }
        lsum[0] = lsum[0] * fct[0] + rsum[0];
        lsum[1] = lsum[1] * fct[1] + rsum[1];
#pragma unroll
        for (int nt = 0; nt < 8; nt++)
#pragma unroll
            for (int r = 0; r < 4; r++) accO[nt][r] *= fct[r >> 1];

        // ---- O += P @ values: C-frag -> A-frag via shfl, tf32 mma ----
#pragma unroll
        for (int kc = 0; kc < 8; kc++) {
            int srcl = g * 4 + (t >> 1);
            float v0 = __shfl_sync(0xffffffffu, accS[kc][0], srcl);
            float v1 = __shfl_sync(0xffffffffu, accS[kc][1], srcl);
            float v2 = __shfl_sync(0xffffffffu, accS[kc][2], srcl);
            float v3 = __shfl_sync(0xffffffffu, accS[kc][3], srcl);
            float w0 = __shfl_sync(0xffffffffu, accS[kc][0], srcl + 2);
            float w1 = __shfl_sync(0xffffffffu, accS[kc][1], srcl + 2);
            float w2 = __shfl_sync(0xffffffffu, accS[kc][2], srcl + 2);
            float w3 = __shfl_sync(0xffffffffu, accS[kc][3], srcl + 2);
            const bool od = t & 1;
            uint32_t ap[4];
            ap[0] = f2tf32(od ? v1 : v0);
            ap[1] = f2tf32(od ? v3 : v2);
            ap[2] = f2tf32(od ? w1 : w0);
            ap[3] = f2tf32(od ? w3 : w2);

            uint32_t vbf[4][4];
#pragma unroll
            for (int p = 0; p < 4; p++) {
                int q = lane >> 3;
                int d = p * 16 + (lane & 7) + ((q >> 1) << 3);
                int c = kc * 2 + (q & 1);
                uint32_t off = d * 256 + ((c ^ (d & 7)) << 4);
                ldsm4(vbf[p], kvb + 16384 + off);
            }
#pragma unroll
            for (int nt = 0; nt < 8; nt++)
                mma_tf32(accO[nt], ap, &vbf[nt >> 1][(nt & 1) * 2]);
        }
        __syncthreads();
    }

    // ---- normalize + write ATT hi/lo planes ----
    const float inv[2] = {1.0f / lsum[0], 1.0f / lsum[1]};
#pragma unroll
    for (int nt = 0; nt < 8; nt++) {
        int d0 = nt * 8 + 2 * t;
#pragma unroll
        for (int rp = 0; rp < 2; rp++) {
            int qrow = q0 + wid * 16 + g + rp * 8;
            float v0 = accO[nt][rp * 2 + 0] * inv[rp];
            float v1 = accO[nt][rp * 2 + 1] * inv[rp];
            size_t o = ((size_t)(b * Lq + qrow)) * Hdim + h * HD + d0;
            split_store2(g_ATTh + o, g_ATTl + o, v0, v1);
        }
    }
}

// ---------------- residual + LayerNorm ---------------------------------------
__global__ __launch_bounds__(256) void ln_k(const float* __restrict__ X,
                                            const float* __restrict__ gamma,
                                            const float* __restrict__ beta,
                                            float* __restrict__ out)
{
    __shared__ float buf[Hdim];
    __shared__ float rs[8], rss[8], stats[2];
    const int m = blockIdx.x;
    const int tid = threadIdx.x;
    const int lane = tid & 31, wid = tid >> 5;

    float s = 0.f, ss = 0.f;
#pragma unroll
    for (int i = 0; i < 4; i++) {
        int hh = i * 256 + tid;
        float v = g_O[(size_t)m * Hdim + hh] + X[(size_t)m * Hdim + hh];
        buf[hh] = v;
        s += v; ss += v * v;
    }
#pragma unroll
    for (int o = 16; o > 0; o >>= 1) {
        s  += __shfl_xor_sync(0xffffffffu, s, o);
        ss += __shfl_xor_sync(0xffffffffu, ss, o);
    }
    if (lane == 0) { rs[wid] = s; rss[wid] = ss; }
    __syncthreads();
    if (tid == 0) {
        float S = 0.f, SS = 0.f;
#pragma unroll
        for (int i = 0; i < 8; i++) { S += rs[i]; SS += rss[i]; }
        float mu = S * (1.0f / Hdim);
        stats[0] = mu;
        stats[1] = rsqrtf(SS * (1.0f / Hdim) - mu * mu + 1e-12f);
    }
    __syncthreads();
    float mu = stats[0], r = stats[1];
#pragma unroll
    for (int i = 0; i < 4; i++) {
        int hh = i * 256 + tid;
        out[(size_t)m * Hdim + hh] = (buf[hh] - mu) * r * gamma[hh] + beta[hh];
    }
}

// ---------------- launch ------------------------------------------------------
extern "C" void kernel_launch(void* const* d_in, const int* in_sizes, int n_in,
                              void* d_out, int out_size)
{
    const float* X     = (const float*)d_in[0];
    const float* mask  = (const float*)d_in[1];
    const float* Wq    = (const float*)d_in[2];
    const float* bq    = (const float*)d_in[3];
    const float* Wk    = (const float*)d_in[4];
    const float* bk    = (const float*)d_in[5];
    const float* Wv    = (const float*)d_in[6];
    const float* bv    = (const float*)d_in[7];
    const float* Wo    = (const float*)d_in[8];
    const float* bo    = (const float*)d_in[9];
    const float* gamma = (const float*)d_in[10];
    const float* beta  = (const float*)d_in[11];

    cudaFuncSetAttribute(gemm_tc, cudaFuncAttributeMaxDynamicSharedMemorySize,
                         GEMM_SMEM_BYTES);
    cudaFuncSetAttribute(attn_k, cudaFuncAttributeMaxDynamicSharedMemorySize,
                         ATTN_SMEM_BYTES);

    split_x<<<(MROWS * Hdim) / 1024, 256>>>(X);
    split_w<<<dim3(Hdim / 32, Hdim / 32, 4), 256>>>(Wq, Wk, Wv, Wo);

    dim3 gg(Hdim / 128, MROWS / 128);   // (8, 32)
    gemm_tc<<<gg, 256, GEMM_SMEM_BYTES>>>(bq, 0);   // Q -> bf16 planes
    gemm_tc<<<gg, 256, GEMM_SMEM_BYTES>>>(bk, 1);   // K-proj = values -> g_Vt
    gemm_tc<<<gg, 256, GEMM_SMEM_BYTES>>>(bv, 2);   // V-proj = keys -> bf16 planes

    attn_k<<<dim3(Lq / 128, NH, Bdim), 256, ATTN_SMEM_BYTES>>>(mask);

    gemm_tc<<<gg, 256, GEMM_SMEM_BYTES>>>(bo, 3);   // O-proj -> g_O fp32

    ln_k<<<MROWS, 256>>>(X, gamma, beta, (float*)d_out);
}

// round 9
// speedup vs baseline: 4.6602x; 1.0329x over previous
#include <cuda_runtime.h>
#include <cuda_bf16.h>
#include <cstdint>

#define Bdim 2
#define Lq 2048
#define Hdim 1024
#define NH 16
#define HD 64
#define MROWS (Bdim * Lq)   // 4096
#define HH (Hdim * Hdim)

// ---------------- scratch (static device arrays; no allocation) --------------
__device__ __nv_bfloat16 g_Xh[(size_t)MROWS * Hdim];
__device__ __nv_bfloat16 g_Xl[(size_t)MROWS * Hdim];
__device__ __nv_bfloat16 g_Wh[(size_t)4 * HH];     // transposed [n][k]: Wq,Wk,Wv,Wo
__device__ __nv_bfloat16 g_Wl[(size_t)4 * HH];
__device__ __nv_bfloat16 g_Qh[(size_t)MROWS * Hdim];   // [bh][l][d]
__device__ __nv_bfloat16 g_Ql[(size_t)MROWS * Hdim];
__device__ __nv_bfloat16 g_Kh[(size_t)MROWS * Hdim];   // keys (= V-proj), [bh][l][d]
__device__ __nv_bfloat16 g_Kl[(size_t)MROWS * Hdim];
__device__ __nv_bfloat16 g_Vb[(size_t)MROWS * Hdim];   // values (= K-proj), [bh][d][l]
__device__ __nv_bfloat16 g_ATTh[(size_t)MROWS * Hdim]; // [b*l][h*64+d]
__device__ __nv_bfloat16 g_ATTl[(size_t)MROWS * Hdim];
__device__ float         g_O[(size_t)MROWS * Hdim];

// ---------------- PTX helpers -------------------------------------------------
__device__ __forceinline__ uint32_t smem_u32(const void* p) {
    uint32_t a;
    asm("{ .reg .u64 t; cvta.to.shared.u64 t, %1; cvt.u32.u64 %0, t; }"
        : "=r"(a) : "l"(p));
    return a;
}
__device__ __forceinline__ void cpa16(uint32_t s, const void* g) {
    asm volatile("cp.async.cg.shared.global [%0], [%1], 16;" :: "r"(s), "l"(g));
}
#define CP_COMMIT() asm volatile("cp.async.commit_group;" ::: "memory")
#define CP_WAIT(n)  asm volatile("cp.async.wait_group %0;" :: "n"(n) : "memory")

__device__ __forceinline__ void ldsm4(uint32_t* r, uint32_t a) {
    asm volatile("ldmatrix.sync.aligned.m8n8.x4.shared.b16 {%0,%1,%2,%3}, [%4];"
                 : "=r"(r[0]), "=r"(r[1]), "=r"(r[2]), "=r"(r[3]) : "r"(a));
}
__device__ __forceinline__ void mma_bf16(float* c, const uint32_t* a, const uint32_t* b) {
    asm volatile(
        "mma.sync.aligned.m16n8k16.row.col.f32.bf16.bf16.f32 "
        "{%0,%1,%2,%3}, {%4,%5,%6,%7}, {%8,%9}, {%0,%1,%2,%3};\n"
        : "+f"(c[0]), "+f"(c[1]), "+f"(c[2]), "+f"(c[3])
        : "r"(a[0]), "r"(a[1]), "r"(a[2]), "r"(a[3]), "r"(b[0]), "r"(b[1]));
}
__device__ __forceinline__ float ex2(float x) {
    float y;
    asm("ex2.approx.f32 %0, %1;" : "=f"(y) : "f"(x));
    return y;
}
__device__ __forceinline__ uint32_t packbf(float a, float b) {
    __nv_bfloat162 h = __floats2bfloat162_rn(a, b);
    return *(uint32_t*)&h;
}
__device__ __forceinline__ void split_store2(__nv_bfloat16* ph, __nv_bfloat16* pl,
                                             float v0, float v1) {
    __nv_bfloat162 h, l;
    h.x = __float2bfloat16(v0); l.x = __float2bfloat16(v0 - __bfloat162float(h.x));
    h.y = __float2bfloat16(v1); l.y = __float2bfloat16(v1 - __bfloat162float(h.y));
    *(__nv_bfloat162*)ph = h;
    *(__nv_bfloat162*)pl = l;
}

// ---------------- preprocessing: split X, transpose+split W -------------------
__global__ __launch_bounds__(256) void split_x(const float* __restrict__ x) {
    int e = (blockIdx.x * 256 + threadIdx.x) * 4;
    float4 v = *(const float4*)(x + e);
    __nv_bfloat162 h0, l0, h1, l1;
    h0.x = __float2bfloat16(v.x); l0.x = __float2bfloat16(v.x - __bfloat162float(h0.x));
    h0.y = __float2bfloat16(v.y); l0.y = __float2bfloat16(v.y - __bfloat162float(h0.y));
    h1.x = __float2bfloat16(v.z); l1.x = __float2bfloat16(v.z - __bfloat162float(h1.x));
    h1.y = __float2bfloat16(v.w); l1.y = __float2bfloat16(v.w - __bfloat162float(h1.y));
    *(__nv_bfloat162*)(g_Xh + e)     = h0;
    *(__nv_bfloat162*)(g_Xl + e)     = l0;
    *(__nv_bfloat162*)(g_Xh + e + 2) = h1;
    *(__nv_bfloat162*)(g_Xl + e + 2) = l1;
}

__global__ __launch_bounds__(256) void split_w(const float* __restrict__ W0,
                                               const float* __restrict__ W1,
                                               const float* __restrict__ W2,
                                               const float* __restrict__ W3) {
    __shared__ float tb[32][33];
    const int w = blockIdx.z;
    const float* src = (w == 0) ? W0 : (w == 1) ? W1 : (w == 2) ? W2 : W3;
    const int k0 = blockIdx.x * 32, n0 = blockIdx.y * 32;
    const int tx = threadIdx.x & 31, ty = threadIdx.x >> 5;  // 32 x 8
#pragma unroll
    for (int i = 0; i < 4; i++) {
        int r = ty + i * 8;
        tb[r][tx] = src[(size_t)(k0 + r) * Hdim + n0 + tx];   // read [k][n]
    }
    __syncthreads();
    __nv_bfloat16* dh = g_Wh + (size_t)w * HH;
    __nv_bfloat16* dl = g_Wl + (size_t)w * HH;
#pragma unroll
    for (int i = 0; i < 4; i++) {
        int r = ty + i * 8;
        float v = tb[tx][r];
        __nv_bfloat16 h = __float2bfloat16(v);
        __nv_bfloat16 l = __float2bfloat16(v - __bfloat162float(h));
        dh[(size_t)(n0 + r) * Hdim + k0 + tx] = h;
        dl[(size_t)(n0 + r) * Hdim + k0 + tx] = l;
    }
}

// ============ GEMM: 128x128x(BK=32) bf16 3-plane, 3-stage pipeline ============
// smem per stage: Ah 8K | Al 8K | Bh 8K | Bl 8K = 32KB; 3 stages = 96KB
#define GEMM_SMEM_BYTES (96 * 1024)
#define NKT 32

__global__ __launch_bounds__(256) void gemm_tc(const float* __restrict__ b0,
                                               const float* __restrict__ b1,
                                               const float* __restrict__ b2,
                                               const float* __restrict__ b3,
                                               int base)
{
    extern __shared__ char smc[];
    const uint32_t sb = smem_u32(smc);
    const int which = base + blockIdx.z;
    const float* __restrict__ bias =
        (which == 0) ? b0 : (which == 1) ? b1 : (which == 2) ? b2 : b3;

    const int tid = threadIdx.x;
    const int wid = tid >> 5, lane = tid & 31;
    const int g = lane >> 2, t = lane & 3;
    const int wm = wid & 3, wn = wid >> 2;            // 4x2 warps, tile 32m x 64n
    const int row0 = blockIdx.y * 128, col0 = blockIdx.x * 128;

    const __nv_bfloat16* __restrict__ Ah_g = (which == 3) ? g_ATTh : g_Xh;
    const __nv_bfloat16* __restrict__ Al_g = (which == 3) ? g_ATTl : g_Xl;
    const __nv_bfloat16* __restrict__ Bh_g = g_Wh + (size_t)which * HH;
    const __nv_bfloat16* __restrict__ Bl_g = g_Wl + (size_t)which * HH;

    float acc[2][8][4];
#pragma unroll
    for (int i = 0; i < 2; i++)
#pragma unroll
        for (int j = 0; j < 8; j++)
#pragma unroll
            for (int r = 0; r < 4; r++) acc[i][j][r] = 0.f;

    auto stage = [&](int kt, int s) {
        const uint32_t ab = sb + s * 32768;
#pragma unroll
        for (int i = 0; i < 2; i++) {
            int e = tid + i * 256;
            int m = e >> 2, c = e & 3;
            uint32_t off = m * 64 + ((c ^ ((m >> 1) & 3)) << 4);
            size_t ga = (size_t)(row0 + m) * Hdim + kt * 32 + c * 8;
            cpa16(ab + off,         Ah_g + ga);
            cpa16(ab + 8192 + off,  Al_g + ga);
            size_t gb = (size_t)(col0 + m) * Hdim + kt * 32 + c * 8;
            cpa16(ab + 16384 + off, Bh_g + gb);
            cpa16(ab + 24576 + off, Bl_g + gb);
        }
        CP_COMMIT();
    };

    stage(0, 0);
    stage(1, 1);
    for (int kt = 0; kt < NKT; kt++) {
        const int s = kt % 3;
        if (kt + 1 < NKT) CP_WAIT(1);
        else              CP_WAIT(0);
        __syncthreads();
        if (kt + 2 < NKT) stage(kt + 2, (kt + 2) % 3);

        const uint32_t ab = sb + s * 32768;
#pragma unroll
        for (int kc = 0; kc < 2; kc++) {
            uint32_t ah[2][4], al[2][4];
#pragma unroll
            for (int mt = 0; mt < 2; mt++) {
                int m = wm * 32 + mt * 16 + (lane & 7) + ((lane >> 3) & 1) * 8;
                int c = kc * 2 + (lane >> 4);
                uint32_t off = m * 64 + ((c ^ ((m >> 1) & 3)) << 4);
                ldsm4(ah[mt], ab + off);
                ldsm4(al[mt], ab + 8192 + off);
            }
            uint32_t bhf[4][4], blf[4][4];
#pragma unroll
            for (int p = 0; p < 4; p++) {
                int q = lane >> 3;
                int n = wn * 64 + p * 16 + (lane & 7) + ((q >> 1) << 3);
                int c = kc * 2 + (q & 1);
                uint32_t off = n * 64 + ((c ^ ((n >> 1) & 3)) << 4);
                ldsm4(bhf[p], ab + 16384 + off);
                ldsm4(blf[p], ab + 24576 + off);
            }
#pragma unroll
            for (int nt = 0; nt < 8; nt++) {
                const uint32_t* bh_ = &bhf[nt >> 1][(nt & 1) * 2];
                const uint32_t* bl_ = &blf[nt >> 1][(nt & 1) * 2];
#pragma unroll
                for (int mt = 0; mt < 2; mt++) {
                    mma_bf16(acc[mt][nt], ah[mt], bh_);
                    mma_bf16(acc[mt][nt], ah[mt], bl_);
                    mma_bf16(acc[mt][nt], al[mt], bh_);
                }
            }
        }
    }

    // epilogue: bias + route to next-stage format
#pragma unroll
    for (int mt = 0; mt < 2; mt++)
#pragma unroll
        for (int nt = 0; nt < 8; nt++) {
            int colb = col0 + wn * 64 + nt * 8 + 2 * t;
            float bb0 = bias[colb], bb1 = bias[colb + 1];
#pragma unroll
            for (int rp = 0; rp < 2; rp++) {
                int row = row0 + wm * 32 + mt * 16 + g + rp * 8;
                float v0 = acc[mt][nt][rp * 2 + 0] + bb0;
                float v1 = acc[mt][nt][rp * 2 + 1] + bb1;
                int bb = row >> 11, l = row & (Lq - 1);
                int h = colb >> 6, d = colb & 63;
                if (which == 0) {
                    size_t o = (((size_t)(bb * NH + h)) * Lq + l) * HD + d;
                    split_store2(g_Qh + o, g_Ql + o, v0, v1);
                } else if (which == 2) {
                    size_t o = (((size_t)(bb * NH + h)) * Lq + l) * HD + d;
                    split_store2(g_Kh + o, g_Kl + o, v0, v1);
                } else if (which == 1) {
                    size_t o = ((size_t)(bb * NH + h) * HD + d) * Lq + l;
                    g_Vb[o]      = __float2bfloat16(v0);
                    g_Vb[o + Lq] = __float2bfloat16(v1);
                } else {
                    float2 v; v.x = v0; v.y = v1;
                    *(float2*)(g_O + (size_t)row * Hdim + colb) = v;
                }
            }
        }
}

// ============ Flash attention (keys = V-proj, values = K-proj) ================
// energies = Q @ keys^T / 4 + mask; attended = softmax @ values
// smem: QH 16K | QL 16K | 2x{ KH 8K | KL 8K | V 8K } | 2x mask 256B = 82432 B
#define NKB (Lq / 64)
#define ATTN_SMEM_BYTES 82432

__global__ __launch_bounds__(256) void attn_k(const float* __restrict__ mask)
{
    extern __shared__ char smc[];
    const uint32_t sb = smem_u32(smc);
    const int tid = threadIdx.x;
    const int wid = tid >> 5, lane = tid & 31;
    const int g = lane >> 2, t = lane & 3;
    const int q0 = blockIdx.x * 128;
    const int h = blockIdx.y, b = blockIdx.z;
    const int bh = b * NH + h;
    const float* __restrict__ maskp = mask + (size_t)b * Lq;

    const float LOG2E = 1.4426950408889634f;
    const float C025  = 0.25f * LOG2E;

    // ---- stage Q (group 0) ----
#pragma unroll
    for (int i = 0; i < 4; i++) {
        int e = tid + i * 256;
        int q = e >> 3, c = e & 7;
        uint32_t off = q * 128 + ((c ^ (q & 7)) << 4);
        size_t ga = (size_t)((size_t)bh * Lq + q0 + q) * HD + c * 8;
        cpa16(sb + off,         g_Qh + ga);
        cpa16(sb + 16384 + off, g_Ql + ga);
    }
    CP_COMMIT();

    auto stageKV = [&](int kb, int s) {
        const int k0 = kb * 64;
        const uint32_t kvb = sb + 32768 + s * 24576;
#pragma unroll
        for (int i = 0; i < 2; i++) {
            int e = tid + i * 256;
            int key = e >> 3, c = e & 7;
            uint32_t off = key * 128 + ((c ^ (key & 7)) << 4);
            size_t ga = (size_t)((size_t)bh * Lq + k0 + key) * HD + c * 8;
            cpa16(kvb + off,        g_Kh + ga);
            cpa16(kvb + 8192 + off, g_Kl + ga);
        }
#pragma unroll
        for (int i = 0; i < 2; i++) {
            int e = tid + i * 256;
            int d = e >> 3, c = e & 7;
            uint32_t off = d * 128 + ((c ^ (d & 7)) << 4);
            cpa16(kvb + 16384 + off, g_Vb + ((size_t)bh * HD + d) * Lq + k0 + c * 8);
        }
        if (tid < 16) cpa16(sb + 81920 + s * 256 + tid * 16, maskp + k0 + tid * 4);
        CP_COMMIT();
    };

    stageKV(0, 0);

    float mprev[2] = {-1e30f, -1e30f};
    float lsum[2]  = {0.f, 0.f};
    float accO[8][4];
#pragma unroll
    for (int nt = 0; nt < 8; nt++)
#pragma unroll
        for (int r = 0; r < 4; r++) accO[nt][r] = 0.f;

    for (int kb = 0; kb < NKB; kb++) {
        const int s = kb & 1;
        if (kb + 1 < NKB) { stageKV(kb + 1, s ^ 1); CP_WAIT(1); }
        else              { CP_WAIT(0); }
        __syncthreads();
        const uint32_t kvb = sb + 32768 + s * 24576;

        // ---- S = Q @ keys^T (bf16 3-plane, k over d=64) ----
        float accS[8][4];
#pragma unroll
        for (int nt = 0; nt < 8; nt++)
#pragma unroll
            for (int r = 0; r < 4; r++) accS[nt][r] = 0.f;

#pragma unroll
        for (int kc = 0; kc < 4; kc++) {
            uint32_t qh[4], ql[4];
            {
                int m = wid * 16 + (lane & 7) + ((lane >> 3) & 1) * 8;
                int c = kc * 2 + (lane >> 4);
                uint32_t off = m * 128 + ((c ^ (m & 7)) << 4);
                ldsm4(qh, sb + off);
                ldsm4(ql, sb + 16384 + off);
            }
            uint32_t kh[4][4], kl[4][4];
#pragma unroll
            for (int p = 0; p < 4; p++) {
                int q = lane >> 3;
                int key = p * 16 + (lane & 7) + ((q >> 1) << 3);
                int c = kc * 2 + (q & 1);
                uint32_t off = key * 128 + ((c ^ (key & 7)) << 4);
                ldsm4(kh[p], kvb + off);
                ldsm4(kl[p], kvb + 8192 + off);
            }
#pragma unroll
            for (int nt = 0; nt < 8; nt++) {
                const uint32_t* bh_ = &kh[nt >> 1][(nt & 1) * 2];
                const uint32_t* bl_ = &kl[nt >> 1][(nt & 1) * 2];
                mma_bf16(accS[nt], qh, bh_);
                mma_bf16(accS[nt], qh, bl_);
                mma_bf16(accS[nt], ql, bh_);
            }
        }

        // ---- scale + mask (log2 domain) ----
        const float* ms = (const float*)(smc + 81920 + s * 256);
#pragma unroll
        for (int nt = 0; nt < 8; nt++) {
            float m0 = ms[nt * 8 + 2 * t]     * LOG2E;
            float m1 = ms[nt * 8 + 2 * t + 1] * LOG2E;
#pragma unroll
            for (int r = 0; r < 4; r++)
                accS[nt][r] = accS[nt][r] * C025 + ((r & 1) ? m1 : m0);
        }

        // ---- online softmax (rows g, g+8), quad reduce ----
        float mx[2] = {-1e30f, -1e30f};
#pragma unroll
        for (int nt = 0; nt < 8; nt++) {
            mx[0] = fmaxf(mx[0], fmaxf(accS[nt][0], accS[nt][1]));
            mx[1] = fmaxf(mx[1], fmaxf(accS[nt][2], accS[nt][3]));
        }
#pragma unroll
        for (int o = 1; o <= 2; o <<= 1) {
            mx[0] = fmaxf(mx[0], __shfl_xor_sync(0xffffffffu, mx[0], o));
            mx[1] = fmaxf(mx[1], __shfl_xor_sync(0xffffffffu, mx[1], o));
        }
        float fct[2], mnew[2], rsum[2] = {0.f, 0.f};
#pragma unroll
        for (int r2 = 0; r2 < 2; r2++) {
            mnew[r2] = fmaxf(mprev[r2], mx[r2]);
            fct[r2]  = ex2(mprev[r2] - mnew[r2]);
            mprev[r2] = mnew[r2];
        }
#pragma unroll
        for (int nt = 0; nt < 8; nt++)
#pragma unroll
            for (int r = 0; r < 4; r++) {
                float p = ex2(accS[nt][r] - mnew[r >> 1]);
                accS[nt][r] = p;
                rsum[r >> 1] += p;
            }
#pragma unroll
        for (int o = 1; o <= 2; o <<= 1) {
            rsum[0] += __shfl_xor_sync(0xffffffffu, rsum[0], o);
            rsum[1] += __shfl_xor_sync(0xffffffffu, rsum[1], o);
        }
        lsum[0] = lsum[0] * fct[0] + rsum[0];
        lsum[1] = lsum[1] * fct[1] + rsum[1];
#pragma unroll
        for (int nt = 0; nt < 8; nt++)
#pragma unroll
            for (int r = 0; r < 4; r++) accO[nt][r] *= fct[r >> 1];

        // ---- O += P @ values: C-frag == A-frag (bf16 k16), zero shuffles ----
#pragma unroll
        for (int kc = 0; kc < 4; kc++) {
            uint32_t ap[4];
            ap[0] = packbf(accS[2 * kc][0],     accS[2 * kc][1]);      // (g,   k2t)
            ap[1] = packbf(accS[2 * kc][2],     accS[2 * kc][3]);      // (g+8, k2t)
            ap[2] = packbf(accS[2 * kc + 1][0], accS[2 * kc + 1][1]);  // (g,   k8+2t)
            ap[3] = packbf(accS[2 * kc + 1][2], accS[2 * kc + 1][3]);  // (g+8, k8+2t)

            uint32_t vbf[4][4];
#pragma unroll
            for (int p = 0; p < 4; p++) {
                int q = lane >> 3;
                int d = p * 16 + ((q >> 1) << 3) + (lane & 7);
                int c = kc * 2 + (q & 1);
                uint32_t off = d * 128 + ((c ^ (d & 7)) << 4);
                ldsm4(vbf[p], kvb + 16384 + off);
            }
#pragma unroll
            for (int nt = 0; nt < 8; nt++)
                mma_bf16(accO[nt], ap, &vbf[nt >> 1][(nt & 1) * 2]);
        }
        __syncthreads();
    }

    // ---- normalize + write ATT hi/lo planes ----
    const float inv[2] = {1.0f / lsum[0], 1.0f / lsum[1]};
#pragma unroll
    for (int nt = 0; nt < 8; nt++) {
        int d0 = nt * 8 + 2 * t;
#pragma unroll
        for (int rp = 0; rp < 2; rp++) {
            int qrow = q0 + wid * 16 + g + rp * 8;
            float v0 = accO[nt][rp * 2 + 0] * inv[rp];
            float v1 = accO[nt][rp * 2 + 1] * inv[rp];
            size_t o = ((size_t)(b * Lq + qrow)) * Hdim + h * HD + d0;
            split_store2(g_ATTh + o, g_ATTl + o, v0, v1);
        }
    }
}

// ---------------- residual + LayerNorm ---------------------------------------
__global__ __launch_bounds__(256) void ln_k(const float* __restrict__ X,
                                            const float* __restrict__ gamma,
                                            const float* __restrict__ beta,
                                            float* __restrict__ out)
{
    __shared__ float buf[Hdim];
    __shared__ float rs[8], rss[8], stats[2];
    const int m = blockIdx.x;
    const int tid = threadIdx.x;
    const int lane = tid & 31, wid = tid >> 5;

    float s = 0.f, ss = 0.f;
#pragma unroll
    for (int i = 0; i < 4; i++) {
        int hh = i * 256 + tid;
        float v = g_O[(size_t)m * Hdim + hh] + X[(size_t)m * Hdim + hh];
        buf[hh] = v;
        s += v; ss += v * v;
    }
#pragma unroll
    for (int o = 16; o > 0; o >>= 1) {
        s  += __shfl_xor_sync(0xffffffffu, s, o);
        ss += __shfl_xor_sync(0xffffffffu, ss, o);
    }
    if (lane == 0) { rs[wid] = s; rss[wid] = ss; }
    __syncthreads();
    if (tid == 0) {
        float S = 0.f, SS = 0.f;
#pragma unroll
        for (int i = 0; i < 8; i++) { S += rs[i]; SS += rss[i]; }
        float mu = S * (1.0f / Hdim);
        stats[0] = mu;
        stats[1] = rsqrtf(SS * (1.0f / Hdim) - mu * mu + 1e-12f);
    }
    __syncthreads();
    float mu = stats[0], r = stats[1];
#pragma unroll
    for (int i = 0; i < 4; i++) {
        int hh = i * 256 + tid;
        out[(size_t)m * Hdim + hh] = (buf[hh] - mu) * r * gamma[hh] + beta[hh];
    }
}

// ---------------- launch ------------------------------------------------------
extern "C" void kernel_launch(void* const* d_in, const int* in_sizes, int n_in,
                              void* d_out, int out_size)
{
    const float* X     = (const float*)d_in[0];
    const float* mask  = (const float*)d_in[1];
    const float* Wq    = (const float*)d_in[2];
    const float* bq    = (const float*)d_in[3];
    const float* Wk    = (const float*)d_in[4];
    const float* bk    = (const float*)d_in[5];
    const float* Wv    = (const float*)d_in[6];
    const float* bv    = (const float*)d_in[7];
    const float* Wo    = (const float*)d_in[8];
    const float* bo    = (const float*)d_in[9];
    const float* gamma = (const float*)d_in[10];
    const float* beta  = (const float*)d_in[11];

    cudaFuncSetAttribute(gemm_tc, cudaFuncAttributeMaxDynamicSharedMemorySize,
                         GEMM_SMEM_BYTES);
    cudaFuncSetAttribute(attn_k, cudaFuncAttributeMaxDynamicSharedMemorySize,
                         ATTN_SMEM_BYTES);

    split_x<<<(MROWS * Hdim) / 1024, 256>>>(X);
    split_w<<<dim3(Hdim / 32, Hdim / 32, 4), 256>>>(Wq, Wk, Wv, Wo);

    // merged QKV projections: z selects {Q, values(K-proj), keys(V-proj)}
    gemm_tc<<<dim3(8, 32, 3), 256, GEMM_SMEM_BYTES>>>(bq, bk, bv, bo, 0);

    attn_k<<<dim3(Lq / 128, NH, Bdim), 256, ATTN_SMEM_BYTES>>>(mask);

    gemm_tc<<<dim3(8, 32, 1), 256, GEMM_SMEM_BYTES>>>(bq, bk, bv, bo, 3);

    ln_k<<<MROWS, 256>>>(X, gamma, beta, (float*)d_out);
}

// round 14
// speedup vs baseline: 5.3436x; 1.1466x over previous
#include <cuda_runtime.h>
#include <cuda_bf16.h>
#include <cuda_fp16.h>
#include <cstdint>

#define Bdim 2
#define Lq 2048
#define Hdim 1024
#define NH 16
#define HD 64
#define MROWS (Bdim * Lq)   // 4096
#define HH (Hdim * Hdim)

// ---------------- scratch (static device arrays; no allocation) --------------
__device__ __nv_bfloat16 g_Xh[(size_t)MROWS * Hdim];
__device__ __nv_bfloat16 g_Xl[(size_t)MROWS * Hdim];
__device__ __nv_bfloat16 g_Wh[(size_t)4 * HH];     // transposed [n][k]: Wq,Wk,Wv,Wo
__device__ __nv_bfloat16 g_Wl[(size_t)4 * HH];
__device__ __half        g_Qf[(size_t)MROWS * Hdim];   // [bh][l][d] fp16
__device__ __half        g_Kf[(size_t)MROWS * Hdim];   // keys (= V-proj), [bh][l][d]
__device__ __half        g_Vf[(size_t)MROWS * Hdim];   // values (= K-proj), [bh][d][l]
__device__ __nv_bfloat16 g_ATTh[(size_t)MROWS * Hdim]; // [b*l][h*64+d]
__device__ __nv_bfloat16 g_ATTl[(size_t)MROWS * Hdim];
__device__ float         g_O[(size_t)MROWS * Hdim];

// ---------------- PTX helpers -------------------------------------------------
__device__ __forceinline__ uint32_t smem_u32(const void* p) {
    uint32_t a;
    asm("{ .reg .u64 t; cvta.to.shared.u64 t, %1; cvt.u32.u64 %0, t; }"
        : "=r"(a) : "l"(p));
    return a;
}
__device__ __forceinline__ void cpa16(uint32_t s, const void* g) {
    asm volatile("cp.async.cg.shared.global [%0], [%1], 16;" :: "r"(s), "l"(g));
}
#define CP_COMMIT() asm volatile("cp.async.commit_group;" ::: "memory")
#define CP_WAIT(n)  asm volatile("cp.async.wait_group %0;" :: "n"(n) : "memory")

__device__ __forceinline__ void ldsm4(uint32_t* r, uint32_t a) {
    asm volatile("ldmatrix.sync.aligned.m8n8.x4.shared.b16 {%0,%1,%2,%3}, [%4];"
                 : "=r"(r[0]), "=r"(r[1]), "=r"(r[2]), "=r"(r[3]) : "r"(a));
}
__device__ __forceinline__ void mma_bf16(float* c, const uint32_t* a, const uint32_t* b) {
    asm volatile(
        "mma.sync.aligned.m16n8k16.row.col.f32.bf16.bf16.f32 "
        "{%0,%1,%2,%3}, {%4,%5,%6,%7}, {%8,%9}, {%0,%1,%2,%3};\n"
        : "+f"(c[0]), "+f"(c[1]), "+f"(c[2]), "+f"(c[3])
        : "r"(a[0]), "r"(a[1]), "r"(a[2]), "r"(a[3]), "r"(b[0]), "r"(b[1]));
}
__device__ __forceinline__ void mma_f16(float* c, const uint32_t* a, const uint32_t* b) {
    asm volatile(
        "mma.sync.aligned.m16n8k16.row.col.f32.f16.f16.f32 "
        "{%0,%1,%2,%3}, {%4,%5,%6,%7}, {%8,%9}, {%0,%1,%2,%3};\n"
        : "+f"(c[0]), "+f"(c[1]), "+f"(c[2]), "+f"(c[3])
        : "r"(a[0]), "r"(a[1]), "r"(a[2]), "r"(a[3]), "r"(b[0]), "r"(b[1]));
}
__device__ __forceinline__ float ex2(float x) {
    float y;
    asm("ex2.approx.f32 %0, %1;" : "=f"(y) : "f"(x));
    return y;
}
__device__ __forceinline__ uint32_t packh(float a, float b) {
    __half2 h = __floats2half2_rn(a, b);
    return *(uint32_t*)&h;
}
__device__ __forceinline__ void split_store2(__nv_bfloat16* ph, __nv_bfloat16* pl,
                                             float v0, float v1) {
    __nv_bfloat162 h, l;
    h.x = __float2bfloat16(v0); l.x = __float2bfloat16(v0 - __bfloat162float(h.x));
    h.y = __float2bfloat16(v1); l.y = __float2bfloat16(v1 - __bfloat162float(h.y));
    *(__nv_bfloat162*)ph = h;
    *(__nv_bfloat162*)pl = l;
}

// ---------------- preprocessing: split X, transpose+split W -------------------
__global__ __launch_bounds__(256) void split_x(const float* __restrict__ x) {
    int e = (blockIdx.x * 256 + threadIdx.x) * 4;
    float4 v = *(const float4*)(x + e);
    __nv_bfloat162 h0, l0, h1, l1;
    h0.x = __float2bfloat16(v.x); l0.x = __float2bfloat16(v.x - __bfloat162float(h0.x));
    h0.y = __float2bfloat16(v.y); l0.y = __float2bfloat16(v.y - __bfloat162float(h0.y));
    h1.x = __float2bfloat16(v.z); l1.x = __float2bfloat16(v.z - __bfloat162float(h1.x));
    h1.y = __float2bfloat16(v.w); l1.y = __float2bfloat16(v.w - __bfloat162float(h1.y));
    *(__nv_bfloat162*)(g_Xh + e)     = h0;
    *(__nv_bfloat162*)(g_Xl + e)     = l0;
    *(__nv_bfloat162*)(g_Xh + e + 2) = h1;
    *(__nv_bfloat162*)(g_Xl + e + 2) = l1;
}

__global__ __launch_bounds__(256) void split_w(const float* __restrict__ W0,
                                               const float* __restrict__ W1,
                                               const float* __restrict__ W2,
                                               const float* __restrict__ W3) {
    __shared__ float tb[32][33];
    const int w = blockIdx.z;
    const float* src = (w == 0) ? W0 : (w == 1) ? W1 : (w == 2) ? W2 : W3;
    const int k0 = blockIdx.x * 32, n0 = blockIdx.y * 32;
    const int tx = threadIdx.x & 31, ty = threadIdx.x >> 5;  // 32 x 8
#pragma unroll
    for (int i = 0; i < 4; i++) {
        int r = ty + i * 8;
        tb[r][tx] = src[(size_t)(k0 + r) * Hdim + n0 + tx];   // read [k][n]
    }
    __syncthreads();
    __nv_bfloat16* dh = g_Wh + (size_t)w * HH;
    __nv_bfloat16* dl = g_Wl + (size_t)w * HH;
#pragma unroll
    for (int i = 0; i < 4; i++) {
        int r = ty + i * 8;
        float v = tb[tx][r];
        __nv_bfloat16 h = __float2bfloat16(v);
        __nv_bfloat16 l = __float2bfloat16(v - __bfloat162float(h));
        dh[(size_t)(n0 + r) * Hdim + k0 + tx] = h;
        dl[(size_t)(n0 + r) * Hdim + k0 + tx] = l;
    }
}

// ============ GEMM: 128x128x(BK=32) bf16 3-plane, 3-stage pipeline ============
// smem per stage: Ah 8K | Al 8K | Bh 8K | Bl 8K = 32KB; 3 stages = 96KB
#define GEMM_SMEM_BYTES (96 * 1024)
#define NKT 32

__global__ __launch_bounds__(256) void gemm_tc(const float* __restrict__ b0,
                                               const float* __restrict__ b1,
                                               const float* __restrict__ b2,
                                               const float* __restrict__ b3,
                                               int base)
{
    extern __shared__ char smc[];
    const uint32_t sb = smem_u32(smc);
    const int which = base + blockIdx.z;
    const float* __restrict__ bias =
        (which == 0) ? b0 : (which == 1) ? b1 : (which == 2) ? b2 : b3;

    const int tid = threadIdx.x;
    const int wid = tid >> 5, lane = tid & 31;
    const int g = lane >> 2, t = lane & 3;
    const int wm = wid & 3, wn = wid >> 2;            // 4x2 warps, tile 32m x 64n
    const int row0 = blockIdx.y * 128, col0 = blockIdx.x * 128;

    const __nv_bfloat16* __restrict__ Ah_g = (which == 3) ? g_ATTh : g_Xh;
    const __nv_bfloat16* __restrict__ Al_g = (which == 3) ? g_ATTl : g_Xl;
    const __nv_bfloat16* __restrict__ Bh_g = g_Wh + (size_t)which * HH;
    const __nv_bfloat16* __restrict__ Bl_g = g_Wl + (size_t)which * HH;

    float acc[2][8][4];
#pragma unroll
    for (int i = 0; i < 2; i++)
#pragma unroll
        for (int j = 0; j < 8; j++)
#pragma unroll
            for (int r = 0; r < 4; r++) acc[i][j][r] = 0.f;

    auto stage = [&](int kt, int s) {
        const uint32_t ab = sb + s * 32768;
#pragma unroll
        for (int i = 0; i < 2; i++) {
            int e = tid + i * 256;
            int m = e >> 2, c = e & 3;
            uint32_t off = m * 64 + ((c ^ ((m >> 1) & 3)) << 4);
            size_t ga = (size_t)(row0 + m) * Hdim + kt * 32 + c * 8;
            cpa16(ab + off,         Ah_g + ga);
            cpa16(ab + 8192 + off,  Al_g + ga);
            size_t gb = (size_t)(col0 + m) * Hdim + kt * 32 + c * 8;
            cpa16(ab + 16384 + off, Bh_g + gb);
            cpa16(ab + 24576 + off, Bl_g + gb);
        }
        CP_COMMIT();
    };

    stage(0, 0);
    stage(1, 1);
    for (int kt = 0; kt < NKT; kt++) {
        const int s = kt % 3;
        if (kt + 1 < NKT) CP_WAIT(1);
        else              CP_WAIT(0);
        __syncthreads();
        if (kt + 2 < NKT) stage(kt + 2, (kt + 2) % 3);

        const uint32_t ab = sb + s * 32768;
#pragma unroll
        for (int kc = 0; kc < 2; kc++) {
            uint32_t ah[2][4], al[2][4];
#pragma unroll
            for (int mt = 0; mt < 2; mt++) {
                int m = wm * 32 + mt * 16 + (lane & 7) + ((lane >> 3) & 1) * 8;
                int c = kc * 2 + (lane >> 4);
                uint32_t off = m * 64 + ((c ^ ((m >> 1) & 3)) << 4);
                ldsm4(ah[mt], ab + off);
                ldsm4(al[mt], ab + 8192 + off);
            }
            uint32_t bhf[4][4], blf[4][4];
#pragma unroll
            for (int p = 0; p < 4; p++) {
                int q = lane >> 3;
                int n = wn * 64 + p * 16 + (lane & 7) + ((q >> 1) << 3);
                int c = kc * 2 + (q & 1);
                uint32_t off = n * 64 + ((c ^ ((n >> 1) & 3)) << 4);
                ldsm4(bhf[p], ab + 16384 + off);
                ldsm4(blf[p], ab + 24576 + off);
            }
#pragma unroll
            for (int nt = 0; nt < 8; nt++) {
                const uint32_t* bh_ = &bhf[nt >> 1][(nt & 1) * 2];
                const uint32_t* bl_ = &blf[nt >> 1][(nt & 1) * 2];
#pragma unroll
                for (int mt = 0; mt < 2; mt++) {
                    mma_bf16(acc[mt][nt], ah[mt], bh_);
                    mma_bf16(acc[mt][nt], ah[mt], bl_);
                    mma_bf16(acc[mt][nt], al[mt], bh_);
                }
            }
        }
    }

    // epilogue: bias + route to next-stage format
#pragma unroll
    for (int mt = 0; mt < 2; mt++)
#pragma unroll
        for (int nt = 0; nt < 8; nt++) {
            int colb = col0 + wn * 64 + nt * 8 + 2 * t;
            float bb0 = bias[colb], bb1 = bias[colb + 1];
#pragma unroll
            for (int rp = 0; rp < 2; rp++) {
                int row = row0 + wm * 32 + mt * 16 + g + rp * 8;
                float v0 = acc[mt][nt][rp * 2 + 0] + bb0;
                float v1 = acc[mt][nt][rp * 2 + 1] + bb1;
                int bb = row >> 11, l = row & (Lq - 1);
                int h = colb >> 6, d = colb & 63;
                if (which == 0) {
                    size_t o = (((size_t)(bb * NH + h)) * Lq + l) * HD + d;
                    *(__half2*)(g_Qf + o) = __floats2half2_rn(v0, v1);
                } else if (which == 2) {
                    size_t o = (((size_t)(bb * NH + h)) * Lq + l) * HD + d;
                    *(__half2*)(g_Kf + o) = __floats2half2_rn(v0, v1);
                } else if (which == 1) {
                    size_t o = ((size_t)(bb * NH + h) * HD + d) * Lq + l;
                    g_Vf[o]      = __float2half_rn(v0);
                    g_Vf[o + Lq] = __float2half_rn(v1);
                } else {
                    float2 v; v.x = v0; v.y = v1;
                    *(float2*)(g_O + (size_t)row * Hdim + colb) = v;
                }
            }
        }
}

// ============ Flash attention, fp16 single-plane (keys=V-proj, values=K-proj) =
// energies = Q @ keys^T / 4 + mask; attended = softmax @ values
// smem: Q 16K | 3 x { K 8K | V 8K } | 3 x mask 256B = 66304 B
#define NKB (Lq / 64)
#define ATTN_SMEM_BYTES 66304

__global__ __launch_bounds__(256, 2) void attn_k(const float* __restrict__ mask)
{
    extern __shared__ char smc[];
    const uint32_t sb = smem_u32(smc);
    const int tid = threadIdx.x;
    const int wid = tid >> 5, lane = tid & 31;
    const int g = lane >> 2, t = lane & 3;
    const int q0 = blockIdx.x * 128;
    const int h = blockIdx.y, b = blockIdx.z;
    const int bh = b * NH + h;
    const float* __restrict__ maskp = mask + (size_t)b * Lq;

    const float LOG2E = 1.4426950408889634f;
    const float C025  = 0.25f * LOG2E;

    // ---- stage Q (own group) ----
#pragma unroll
    for (int i = 0; i < 4; i++) {
        int e = tid + i * 256;
        int q = e >> 3, c = e & 7;
        uint32_t off = q * 128 + ((c ^ (q & 7)) << 4);
        cpa16(sb + off, g_Qf + (size_t)((size_t)bh * Lq + q0 + q) * HD + c * 8);
    }
    CP_COMMIT();

    auto stageKV = [&](int kb, int s) {
        const int k0 = kb * 64;
        const uint32_t kvb = sb + 16384 + s * 16384;
#pragma unroll
        for (int i = 0; i < 2; i++) {
            int e = tid + i * 256;
            int row = e >> 3, c = e & 7;
            uint32_t off = row * 128 + ((c ^ (row & 7)) << 4);
            cpa16(kvb + off,
                  g_Kf + (size_t)((size_t)bh * Lq + k0 + row) * HD + c * 8);
            cpa16(kvb + 8192 + off,
                  g_Vf + ((size_t)bh * HD + row) * Lq + k0 + c * 8);
        }
        if (tid < 16) cpa16(sb + 65536 + s * 256 + tid * 16, maskp + k0 + tid * 4);
        CP_COMMIT();
    };

    stageKV(0, 0);
    stageKV(1, 1);

    uint32_t qf[4][4];            // Q fragments, register-resident
    float mprev[2] = {-1e30f, -1e30f};
    float lsum[2]  = {0.f, 0.f};
    float accO[8][4];
#pragma unroll
    for (int nt = 0; nt < 8; nt++)
#pragma unroll
        for (int r = 0; r < 4; r++) accO[nt][r] = 0.f;

    for (int kb = 0; kb < NKB; kb++) {
        const int s = kb % 3;
        if (kb + 1 < NKB) CP_WAIT(1);
        else              CP_WAIT(0);
        __syncthreads();
        if (kb + 2 < NKB) stageKV(kb + 2, (kb + 2) % 3);

        if (kb == 0) {
            // load Q fragments once
#pragma unroll
            for (int kc = 0; kc < 4; kc++) {
                int m = wid * 16 + (lane & 7) + ((lane >> 3) & 1) * 8;
                int c = kc * 2 + (lane >> 4);
                uint32_t off = m * 128 + ((c ^ (m & 7)) << 4);
                ldsm4(qf[kc], sb + off);
            }
        }

        const uint32_t kvb = sb + 16384 + s * 16384;

        // ---- S = Q @ keys^T (fp16, k over d=64) ----
        float accS[8][4];
#pragma unroll
        for (int nt = 0; nt < 8; nt++)
#pragma unroll
            for (int r = 0; r < 4; r++) accS[nt][r] = 0.f;

#pragma unroll
        for (int kc = 0; kc < 4; kc++) {
            uint32_t kh[4][4];
#pragma unroll
            for (int p = 0; p < 4; p++) {
                int q = lane >> 3;
                int key = p * 16 + (lane & 7) + ((q >> 1) << 3);
                int c = kc * 2 + (q & 1);
                uint32_t off = key * 128 + ((c ^ (key & 7)) << 4);
                ldsm4(kh[p], kvb + off);
            }
#pragma unroll
            for (int nt = 0; nt < 8; nt++)
                mma_f16(accS[nt], qf[kc], &kh[nt >> 1][(nt & 1) * 2]);
        }

        // ---- scale + mask (log2 domain) ----
        const float* ms = (const float*)(smc + 65536 + s * 256);
#pragma unroll
        for (int nt = 0; nt < 8; nt++) {
            float m0 = ms[nt * 8 + 2 * t]     * LOG2E;
            float m1 = ms[nt * 8 + 2 * t + 1] * LOG2E;
#pragma unroll
            for (int r = 0; r < 4; r++)
                accS[nt][r] = accS[nt][r] * C025 + ((r & 1) ? m1 : m0);
        }

        // ---- online softmax (rows g, g+8), quad reduce ----
        float mx[2] = {-1e30f, -1e30f};
#pragma unroll
        for (int nt = 0; nt < 8; nt++) {
            mx[0] = fmaxf(mx[0], fmaxf(accS[nt][0], accS[nt][1]));
            mx[1] = fmaxf(mx[1], fmaxf(accS[nt][2], accS[nt][3]));
        }
#pragma unroll
        for (int o = 1; o <= 2; o <<= 1) {
            mx[0] = fmaxf(mx[0], __shfl_xor_sync(0xffffffffu, mx[0], o));
            mx[1] = fmaxf(mx[1], __shfl_xor_sync(0xffffffffu, mx[1], o));
        }
        float fct[2], mnew[2], rsum[2] = {0.f, 0.f};
#pragma unroll
        for (int r2 = 0; r2 < 2; r2++) {
            mnew[r2] = fmaxf(mprev[r2], mx[r2]);
            fct[r2]  = ex2(mprev[r2] - mnew[r2]);
            mprev[r2] = mnew[r2];
        }
#pragma unroll
        for (int nt = 0; nt < 8; nt++)
#pragma unroll
            for (int r = 0; r < 4; r++) {
                float p = ex2(accS[nt][r] - mnew[r >> 1]);
                accS[nt][r] = p;
                rsum[r >> 1] += p;
            }
#pragma unroll
        for (int o = 1; o <= 2; o <<= 1) {
            rsum[0] += __shfl_xor_sync(0xffffffffu, rsum[0], o);
            rsum[1] += __shfl_xor_sync(0xffffffffu, rsum[1], o);
        }
        lsum[0] = lsum[0] * fct[0] + rsum[0];
        lsum[1] = lsum[1] * fct[1] + rsum[1];
#pragma unroll
        for (int nt = 0; nt < 8; nt++)
#pragma unroll
            for (int r = 0; r < 4; r++) accO[nt][r] *= fct[r >> 1];

        // ---- O += P @ values: C-frag == A-frag (fp16 k16), zero shuffles ----
#pragma unroll
        for (int kc = 0; kc < 4; kc++) {
            uint32_t ap[4];
            ap[0] = packh(accS[2 * kc][0],     accS[2 * kc][1]);
            ap[1] = packh(accS[2 * kc][2],     accS[2 * kc][3]);
            ap[2] = packh(accS[2 * kc + 1][0], accS[2 * kc + 1][1]);
            ap[3] = packh(accS[2 * kc + 1][2], accS[2 * kc + 1][3]);

            uint32_t vf[4][4];
#pragma unroll
            for (int p = 0; p < 4; p++) {
                int q = lane >> 3;
                int d = p * 16 + ((q >> 1) << 3) + (lane & 7);
                int c = kc * 2 + (q & 1);
                uint32_t off = d * 128 + ((c ^ (d & 7)) << 4);
                ldsm4(vf[p], kvb + 8192 + off);
            }
#pragma unroll
            for (int nt = 0; nt < 8; nt++)
                mma_f16(accO[nt], ap, &vf[nt >> 1][(nt & 1) * 2]);
        }
    }

    // ---- normalize + write ATT hi/lo planes ----
    const float inv[2] = {1.0f / lsum[0], 1.0f / lsum[1]};
#pragma unroll
    for (int nt = 0; nt < 8; nt++) {
        int d0 = nt * 8 + 2 * t;
#pragma unroll
        for (int rp = 0; rp < 2; rp++) {
            int qrow = q0 + wid * 16 + g + rp * 8;
            float v0 = accO[nt][rp * 2 + 0] * inv[rp];
            float v1 = accO[nt][rp * 2 + 1] * inv[rp];
            size_t o = ((size_t)(b * Lq + qrow)) * Hdim + h * HD + d0;
            split_store2(g_ATTh + o, g_ATTl + o, v0, v1);
        }
    }
}

// ---------------- residual + LayerNorm ---------------------------------------
__global__ __launch_bounds__(256) void ln_k(const float* __restrict__ X,
                                            const float* __restrict__ gamma,
                                            const float* __restrict__ beta,
                                            float* __restrict__ out)
{
    __shared__ float buf[Hdim];
    __shared__ float rs[8], rss[8], stats[2];
    const int m = blockIdx.x;
    const int tid = threadIdx.x;
    const int lane = tid & 31, wid = tid >> 5;

    float s = 0.f, ss = 0.f;
#pragma unroll
    for (int i = 0; i < 4; i++) {
        int hh = i * 256 + tid;
        float v = g_O[(size_t)m * Hdim + hh] + X[(size_t)m * Hdim + hh];
        buf[hh] = v;
        s += v; ss += v * v;
    }
#pragma unroll
    for (int o = 16; o > 0; o >>= 1) {
        s  += __shfl_xor_sync(0xffffffffu, s, o);
        ss += __shfl_xor_sync(0xffffffffu, ss, o);
    }
    if (lane == 0) { rs[wid] = s; rss[wid] = ss; }
    __syncthreads();
    if (tid == 0) {
        float S = 0.f, SS = 0.f;
#pragma unroll
        for (int i = 0; i < 8; i++) { S += rs[i]; SS += rss[i]; }
        float mu = S * (1.0f / Hdim);
        stats[0] = mu;
        stats[1] = rsqrtf(SS * (1.0f / Hdim) - mu * mu + 1e-12f);
    }
    __syncthreads();
    float mu = stats[0], r = stats[1];
#pragma unroll
    for (int i = 0; i < 4; i++) {
        int hh = i * 256 + tid;
        out[(size_t)m * Hdim + hh] = (buf[hh] - mu) * r * gamma[hh] + beta[hh];
    }
}

// ---------------- launch ------------------------------------------------------
extern "C" void kernel_launch(void* const* d_in, const int* in_sizes, int n_in,
                              void* d_out, int out_size)
{
    const float* X     = (const float*)d_in[0];
    const float* mask  = (const float*)d_in[1];
    const float* Wq    = (const float*)d_in[2];
    const float* bq    = (const float*)d_in[3];
    const float* Wk    = (const float*)d_in[4];
    const float* bk    = (const float*)d_in[5];
    const float* Wv    = (const float*)d_in[6];
    const float* bv    = (const float*)d_in[7];
    const float* Wo    = (const float*)d_in[8];
    const float* bo    = (const float*)d_in[9];
    const float* gamma = (const float*)d_in[10];
    const float* beta  = (const float*)d_in[11];

    cudaFuncSetAttribute(gemm_tc, cudaFuncAttributeMaxDynamicSharedMemorySize,
                         GEMM_SMEM_BYTES);
    cudaFuncSetAttribute(attn_k, cudaFuncAttributeMaxDynamicSharedMemorySize,
                         ATTN_SMEM_BYTES);

    split_x<<<(MROWS * Hdim) / 1024, 256>>>(X);
    split_w<<<dim3(Hdim / 32, Hdim / 32, 4), 256>>>(Wq, Wk, Wv, Wo);

    // merged QKV projections: z selects {Q, values(K-proj), keys(V-proj)}
    gemm_tc<<<dim3(8, 32, 3), 256, GEMM_SMEM_BYTES>>>(bq, bk, bv, bo, 0);

    attn_k<<<dim3(Lq / 128, NH, Bdim), 256, ATTN_SMEM_BYTES>>>(mask);

    gemm_tc<<<dim3(8, 32, 1), 256, GEMM_SMEM_BYTES>>>(bq, bk, bv, bo, 3);

    ln_k<<<MROWS, 256>>>(X, gamma, beta, (float*)d_out);
}

// round 15
// speedup vs baseline: 8.3701x; 1.5664x over previous
#include <cuda_runtime.h>
#include <cuda_bf16.h>
#include <cuda_fp16.h>
#include <cstdint>

#define Bdim 2
#define Lq 2048
#define Hdim 1024
#define NH 16
#define HD 64
#define MROWS (Bdim * Lq)   // 4096
#define HH (Hdim * Hdim)

// ---------------- scratch (static device arrays; no allocation) --------------
__device__ __half        g_Xf[(size_t)MROWS * Hdim];   // fp16 activations
__device__ __half        g_Wf[(size_t)3 * HH];         // fp16 [n][k]: Wq,Wk,Wv
__device__ __nv_bfloat16 g_Woh[(size_t)HH];            // Wo bf16 hi, [n][k]
__device__ __nv_bfloat16 g_Wol[(size_t)HH];            // Wo bf16 lo
__device__ __half        g_Qf[(size_t)MROWS * Hdim];   // [bh][l][d] fp16
__device__ __half        g_Kf[(size_t)MROWS * Hdim];   // keys (= V-proj), [bh][l][d]
__device__ __half        g_Vf[(size_t)MROWS * Hdim];   // values (= K-proj), [bh][d][l]
__device__ __nv_bfloat16 g_ATTh[(size_t)MROWS * Hdim]; // [b*l][h*64+d]
__device__ __nv_bfloat16 g_ATTl[(size_t)MROWS * Hdim];
__device__ float         g_O[(size_t)MROWS * Hdim];

// ---------------- PTX helpers -------------------------------------------------
__device__ __forceinline__ uint32_t smem_u32(const void* p) {
    uint32_t a;
    asm("{ .reg .u64 t; cvta.to.shared.u64 t, %1; cvt.u32.u64 %0, t; }"
        : "=r"(a) : "l"(p));
    return a;
}
__device__ __forceinline__ void cpa16(uint32_t s, const void* g) {
    asm volatile("cp.async.cg.shared.global [%0], [%1], 16;" :: "r"(s), "l"(g));
}
#define CP_COMMIT() asm volatile("cp.async.commit_group;" ::: "memory")
#define CP_WAIT(n)  asm volatile("cp.async.wait_group %0;" :: "n"(n) : "memory")

__device__ __forceinline__ void ldsm4(uint32_t* r, uint32_t a) {
    asm volatile("ldmatrix.sync.aligned.m8n8.x4.shared.b16 {%0,%1,%2,%3}, [%4];"
                 : "=r"(r[0]), "=r"(r[1]), "=r"(r[2]), "=r"(r[3]) : "r"(a));
}
__device__ __forceinline__ void mma_bf16(float* c, const uint32_t* a, const uint32_t* b) {
    asm volatile(
        "mma.sync.aligned.m16n8k16.row.col.f32.bf16.bf16.f32 "
        "{%0,%1,%2,%3}, {%4,%5,%6,%7}, {%8,%9}, {%0,%1,%2,%3};\n"
        : "+f"(c[0]), "+f"(c[1]), "+f"(c[2]), "+f"(c[3])
        : "r"(a[0]), "r"(a[1]), "r"(a[2]), "r"(a[3]), "r"(b[0]), "r"(b[1]));
}
__device__ __forceinline__ void mma_f16(float* c, const uint32_t* a, const uint32_t* b) {
    asm volatile(
        "mma.sync.aligned.m16n8k16.row.col.f32.f16.f16.f32 "
        "{%0,%1,%2,%3}, {%4,%5,%6,%7}, {%8,%9}, {%0,%1,%2,%3};\n"
        : "+f"(c[0]), "+f"(c[1]), "+f"(c[2]), "+f"(c[3])
        : "r"(a[0]), "r"(a[1]), "r"(a[2]), "r"(a[3]), "r"(b[0]), "r"(b[1]));
}
__device__ __forceinline__ float ex2(float x) {
    float y;
    asm("ex2.approx.f32 %0, %1;" : "=f"(y) : "f"(x));
    return y;
}
__device__ __forceinline__ uint32_t packh(float a, float b) {
    __half2 h = __floats2half2_rn(a, b);
    return *(uint32_t*)&h;
}
__device__ __forceinline__ void split_store2(__nv_bfloat16* ph, __nv_bfloat16* pl,
                                             float v0, float v1) {
    __nv_bfloat162 h, l;
    h.x = __float2bfloat16(v0); l.x = __float2bfloat16(v0 - __bfloat162float(h.x));
    h.y = __float2bfloat16(v1); l.y = __float2bfloat16(v1 - __bfloat162float(h.y));
    *(__nv_bfloat162*)ph = h;
    *(__nv_bfloat162*)pl = l;
}

// ---------------- preprocessing -----------------------------------------------
__global__ __launch_bounds__(256) void split_x(const float* __restrict__ x) {
    int e = (blockIdx.x * 256 + threadIdx.x) * 4;
    float4 v = *(const float4*)(x + e);
    *(__half2*)(g_Xf + e)     = __floats2half2_rn(v.x, v.y);
    *(__half2*)(g_Xf + e + 2) = __floats2half2_rn(v.z, v.w);
}

// transpose weights; w<3 -> fp16 single plane, w==3 -> bf16 hi/lo planes
__global__ __launch_bounds__(256) void split_w(const float* __restrict__ W0,
                                               const float* __restrict__ W1,
                                               const float* __restrict__ W2,
                                               const float* __restrict__ W3) {
    __shared__ float tb[32][33];
    const int w = blockIdx.z;
    const float* src = (w == 0) ? W0 : (w == 1) ? W1 : (w == 2) ? W2 : W3;
    const int k0 = blockIdx.x * 32, n0 = blockIdx.y * 32;
    const int tx = threadIdx.x & 31, ty = threadIdx.x >> 5;  // 32 x 8
#pragma unroll
    for (int i = 0; i < 4; i++) {
        int r = ty + i * 8;
        tb[r][tx] = src[(size_t)(k0 + r) * Hdim + n0 + tx];   // read [k][n]
    }
    __syncthreads();
    if (w < 3) {
        __half* d = g_Wf + (size_t)w * HH;
#pragma unroll
        for (int i = 0; i < 4; i++) {
            int r = ty + i * 8;
            d[(size_t)(n0 + r) * Hdim + k0 + tx] = __float2half_rn(tb[tx][r]);
        }
    } else {
#pragma unroll
        for (int i = 0; i < 4; i++) {
            int r = ty + i * 8;
            float v = tb[tx][r];
            __nv_bfloat16 h = __float2bfloat16(v);
            __nv_bfloat16 l = __float2bfloat16(v - __bfloat162float(h));
            g_Woh[(size_t)(n0 + r) * Hdim + k0 + tx] = h;
            g_Wol[(size_t)(n0 + r) * Hdim + k0 + tx] = l;
        }
    }
}

// ============ QKV GEMM: 128x128x(BK=64) fp16 single-plane, 3-stage ===========
// smem per stage: A 16K | B 16K = 32KB; 3 stages = 96KB
#define QKV_SMEM_BYTES (96 * 1024)
#define NKT2 16   // 1024 / 64

__global__ __launch_bounds__(256) void gemm_qkv(const float* __restrict__ b0,
                                                const float* __restrict__ b1,
                                                const float* __restrict__ b2)
{
    extern __shared__ char smc[];
    const uint32_t sb = smem_u32(smc);
    const int which = blockIdx.z;
    const float* __restrict__ bias = (which == 0) ? b0 : (which == 1) ? b1 : b2;

    const int tid = threadIdx.x;
    const int wid = tid >> 5, lane = tid & 31;
    const int g = lane >> 2, t = lane & 3;
    const int wm = wid & 3, wn = wid >> 2;            // 4x2 warps, tile 32m x 64n
    const int row0 = blockIdx.y * 128, col0 = blockIdx.x * 128;

    const __half* __restrict__ Bw = g_Wf + (size_t)which * HH;

    float acc[2][8][4];
#pragma unroll
    for (int i = 0; i < 2; i++)
#pragma unroll
        for (int j = 0; j < 8; j++)
#pragma unroll
            for (int r = 0; r < 4; r++) acc[i][j][r] = 0.f;

    auto stage = [&](int kt, int s) {
        const uint32_t ab = sb + s * 32768;
#pragma unroll
        for (int i = 0; i < 4; i++) {
            int e = tid + i * 256;           // 1024: A 128 rows x 8 chunks
            int m = e >> 3, c = e & 7;
            uint32_t off = m * 128 + ((c ^ (m & 7)) << 4);
            cpa16(ab + off, g_Xf + (size_t)(row0 + m) * Hdim + kt * 64 + c * 8);
        }
#pragma unroll
        for (int i = 0; i < 4; i++) {
            int e = tid + i * 256;           // 1024: B 128 rows x 8 chunks
            int n = e >> 3, c = e & 7;
            uint32_t off = n * 128 + ((c ^ (n & 7)) << 4);
            cpa16(ab + 16384 + off, Bw + (size_t)(col0 + n) * Hdim + kt * 64 + c * 8);
        }
        CP_COMMIT();
    };

    stage(0, 0);
    stage(1, 1);
    for (int kt = 0; kt < NKT2; kt++) {
        const int s = kt % 3;
        if (kt + 1 < NKT2) CP_WAIT(1);
        else               CP_WAIT(0);
        __syncthreads();
        if (kt + 2 < NKT2) stage(kt + 2, (kt + 2) % 3);

        const uint32_t ab = sb + s * 32768;
#pragma unroll
        for (int kc = 0; kc < 4; kc++) {
            uint32_t af[2][4];
#pragma unroll
            for (int mt = 0; mt < 2; mt++) {
                int m = wm * 32 + mt * 16 + (lane & 7) + ((lane >> 3) & 1) * 8;
                int c = kc * 2 + (lane >> 4);
                uint32_t off = m * 128 + ((c ^ (m & 7)) << 4);
                ldsm4(af[mt], ab + off);
            }
            uint32_t bf[4][4];
#pragma unroll
            for (int p = 0; p < 4; p++) {
                int q = lane >> 3;
                int n = wn * 64 + p * 16 + (lane & 7) + ((q >> 1) << 3);
                int c = kc * 2 + (q & 1);
                uint32_t off = n * 128 + ((c ^ (n & 7)) << 4);
                ldsm4(bf[p], ab + 16384 + off);
            }
#pragma unroll
            for (int nt = 0; nt < 8; nt++)
#pragma unroll
                for (int mt = 0; mt < 2; mt++)
                    mma_f16(acc[mt][nt], af[mt], &bf[nt >> 1][(nt & 1) * 2]);
        }
    }

    // epilogue: bias + route to attention layouts (fp16)
#pragma unroll
    for (int mt = 0; mt < 2; mt++)
#pragma unroll
        for (int nt = 0; nt < 8; nt++) {
            int colb = col0 + wn * 64 + nt * 8 + 2 * t;
            float bb0 = bias[colb], bb1 = bias[colb + 1];
#pragma unroll
            for (int rp = 0; rp < 2; rp++) {
                int row = row0 + wm * 32 + mt * 16 + g + rp * 8;
                float v0 = acc[mt][nt][rp * 2 + 0] + bb0;
                float v1 = acc[mt][nt][rp * 2 + 1] + bb1;
                int bb = row >> 11, l = row & (Lq - 1);
                int h = colb >> 6, d = colb & 63;
                if (which == 0) {
                    size_t o = (((size_t)(bb * NH + h)) * Lq + l) * HD + d;
                    *(__half2*)(g_Qf + o) = __floats2half2_rn(v0, v1);
                } else if (which == 2) {
                    size_t o = (((size_t)(bb * NH + h)) * Lq + l) * HD + d;
                    *(__half2*)(g_Kf + o) = __floats2half2_rn(v0, v1);
                } else {
                    size_t o = ((size_t)(bb * NH + h) * HD + d) * Lq + l;
                    g_Vf[o]      = __float2half_rn(v0);
                    g_Vf[o + Lq] = __float2half_rn(v1);
                }
            }
        }
}

// ============ O-proj GEMM: 128x128x(BK=32) bf16 3-plane, 3-stage ==============
#define GEMM_SMEM_BYTES (96 * 1024)
#define NKT 32

__global__ __launch_bounds__(256) void gemm_o(const float* __restrict__ bias)
{
    extern __shared__ char smc[];
    const uint32_t sb = smem_u32(smc);
    const int tid = threadIdx.x;
    const int wid = tid >> 5, lane = tid & 31;
    const int g = lane >> 2, t = lane & 3;
    const int wm = wid & 3, wn = wid >> 2;
    const int row0 = blockIdx.y * 128, col0 = blockIdx.x * 128;

    float acc[2][8][4];
#pragma unroll
    for (int i = 0; i < 2; i++)
#pragma unroll
        for (int j = 0; j < 8; j++)
#pragma unroll
            for (int r = 0; r < 4; r++) acc[i][j][r] = 0.f;

    auto stage = [&](int kt, int s) {
        const uint32_t ab = sb + s * 32768;
#pragma unroll
        for (int i = 0; i < 2; i++) {
            int e = tid + i * 256;
            int m = e >> 2, c = e & 3;
            uint32_t off = m * 64 + ((c ^ ((m >> 1) & 3)) << 4);
            size_t ga = (size_t)(row0 + m) * Hdim + kt * 32 + c * 8;
            cpa16(ab + off,         g_ATTh + ga);
            cpa16(ab + 8192 + off,  g_ATTl + ga);
            size_t gb = (size_t)(col0 + m) * Hdim + kt * 32 + c * 8;
            cpa16(ab + 16384 + off, g_Woh + gb);
            cpa16(ab + 24576 + off, g_Wol + gb);
        }
        CP_COMMIT();
    };

    stage(0, 0);
    stage(1, 1);
    for (int kt = 0; kt < NKT; kt++) {
        const int s = kt % 3;
        if (kt + 1 < NKT) CP_WAIT(1);
        else              CP_WAIT(0);
        __syncthreads();
        if (kt + 2 < NKT) stage(kt + 2, (kt + 2) % 3);

        const uint32_t ab = sb + s * 32768;
#pragma unroll
        for (int kc = 0; kc < 2; kc++) {
            uint32_t ah[2][4], al[2][4];
#pragma unroll
            for (int mt = 0; mt < 2; mt++) {
                int m = wm * 32 + mt * 16 + (lane & 7) + ((lane >> 3) & 1) * 8;
                int c = kc * 2 + (lane >> 4);
                uint32_t off = m * 64 + ((c ^ ((m >> 1) & 3)) << 4);
                ldsm4(ah[mt], ab + off);
                ldsm4(al[mt], ab + 8192 + off);
            }
            uint32_t bhf[4][4], blf[4][4];
#pragma unroll
            for (int p = 0; p < 4; p++) {
                int q = lane >> 3;
                int n = wn * 64 + p * 16 + (lane & 7) + ((q >> 1) << 3);
                int c = kc * 2 + (q & 1);
                uint32_t off = n * 64 + ((c ^ ((n >> 1) & 3)) << 4);
                ldsm4(bhf[p], ab + 16384 + off);
                ldsm4(blf[p], ab + 24576 + off);
            }
#pragma unroll
            for (int nt = 0; nt < 8; nt++) {
                const uint32_t* bh_ = &bhf[nt >> 1][(nt & 1) * 2];
                const uint32_t* bl_ = &blf[nt >> 1][(nt & 1) * 2];
#pragma unroll
                for (int mt = 0; mt < 2; mt++) {
                    mma_bf16(acc[mt][nt], ah[mt], bh_);
                    mma_bf16(acc[mt][nt], ah[mt], bl_);
                    mma_bf16(acc[mt][nt], al[mt], bh_);
                }
            }
        }
    }

#pragma unroll
    for (int mt = 0; mt < 2; mt++)
#pragma unroll
        for (int nt = 0; nt < 8; nt++) {
            int colb = col0 + wn * 64 + nt * 8 + 2 * t;
            float bb0 = bias[colb], bb1 = bias[colb + 1];
#pragma unroll
            for (int rp = 0; rp < 2; rp++) {
                int row = row0 + wm * 32 + mt * 16 + g + rp * 8;
                float2 v;
                v.x = acc[mt][nt][rp * 2 + 0] + bb0;
                v.y = acc[mt][nt][rp * 2 + 1] + bb1;
                *(float2*)(g_O + (size_t)row * Hdim + colb) = v;
            }
        }
}

// ============ Flash attention, fp16 single-plane (keys=V-proj, values=K-proj) =
// energies = Q @ keys^T / 4 + mask; attended = softmax @ values
// smem: Q 16K | 3 x { K 8K | V 8K } | 3 x mask 256B = 66304 B
#define NKB (Lq / 64)
#define ATTN_SMEM_BYTES 66304

__global__ __launch_bounds__(256, 2) void attn_k(const float* __restrict__ mask)
{
    extern __shared__ char smc[];
    const uint32_t sb = smem_u32(smc);
    const int tid = threadIdx.x;
    const int wid = tid >> 5, lane = tid & 31;
    const int g = lane >> 2, t = lane & 3;
    const int q0 = blockIdx.x * 128;
    const int h = blockIdx.y, b = blockIdx.z;
    const int bh = b * NH + h;
    const float* __restrict__ maskp = mask + (size_t)b * Lq;

    const float LOG2E = 1.4426950408889634f;
    const float C025  = 0.25f * LOG2E;

#pragma unroll
    for (int i = 0; i < 4; i++) {
        int e = tid + i * 256;
        int q = e >> 3, c = e & 7;
        uint32_t off = q * 128 + ((c ^ (q & 7)) << 4);
        cpa16(sb + off, g_Qf + (size_t)((size_t)bh * Lq + q0 + q) * HD + c * 8);
    }
    CP_COMMIT();

    auto stageKV = [&](int kb, int s) {
        const int k0 = kb * 64;
        const uint32_t kvb = sb + 16384 + s * 16384;
#pragma unroll
        for (int i = 0; i < 2; i++) {
            int e = tid + i * 256;
            int row = e >> 3, c = e & 7;
            uint32_t off = row * 128 + ((c ^ (row & 7)) << 4);
            cpa16(kvb + off,
                  g_Kf + (size_t)((size_t)bh * Lq + k0 + row) * HD + c * 8);
            cpa16(kvb + 8192 + off,
                  g_Vf + ((size_t)bh * HD + row) * Lq + k0 + c * 8);
        }
        if (tid < 16) cpa16(sb + 65536 + s * 256 + tid * 16, maskp + k0 + tid * 4);
        CP_COMMIT();
    };

    stageKV(0, 0);
    stageKV(1, 1);

    uint32_t qf[4][4];
    float mprev[2] = {-1e30f, -1e30f};
    float lsum[2]  = {0.f, 0.f};
    float accO[8][4];
#pragma unroll
    for (int nt = 0; nt < 8; nt++)
#pragma unroll
        for (int r = 0; r < 4; r++) accO[nt][r] = 0.f;

    for (int kb = 0; kb < NKB; kb++) {
        const int s = kb % 3;
        if (kb + 1 < NKB) CP_WAIT(1);
        else              CP_WAIT(0);
        __syncthreads();
        if (kb + 2 < NKB) stageKV(kb + 2, (kb + 2) % 3);

        if (kb == 0) {
#pragma unroll
            for (int kc = 0; kc < 4; kc++) {
                int m = wid * 16 + (lane & 7) + ((lane >> 3) & 1) * 8;
                int c = kc * 2 + (lane >> 4);
                uint32_t off = m * 128 + ((c ^ (m & 7)) << 4);
                ldsm4(qf[kc], sb + off);
            }
        }

        const uint32_t kvb = sb + 16384 + s * 16384;

        float accS[8][4];
#pragma unroll
        for (int nt = 0; nt < 8; nt++)
#pragma unroll
            for (int r = 0; r < 4; r++) accS[nt][r] = 0.f;

#pragma unroll
        for (int kc = 0; kc < 4; kc++) {
            uint32_t kh[4][4];
#pragma unroll
            for (int p = 0; p < 4; p++) {
                int q = lane >> 3;
                int key = p * 16 + (lane & 7) + ((q >> 1) << 3);
                int c = kc * 2 + (q & 1);
                uint32_t off = key * 128 + ((c ^ (key & 7)) << 4);
                ldsm4(kh[p], kvb + off);
            }
#pragma unroll
            for (int nt = 0; nt < 8; nt++)
                mma_f16(accS[nt], qf[kc], &kh[nt >> 1][(nt & 1) * 2]);
        }

        const float* ms = (const float*)(smc + 65536 + s * 256);
#pragma unroll
        for (int nt = 0; nt < 8; nt++) {
            float m0 = ms[nt * 8 + 2 * t]     * LOG2E;
            float m1 = ms[nt * 8 + 2 * t + 1] * LOG2E;
#pragma unroll
            for (int r = 0; r < 4; r++)
                accS[nt][r] = accS[nt][r] * C025 + ((r & 1) ? m1 : m0);
        }

        float mx[2] = {-1e30f, -1e30f};
#pragma unroll
        for (int nt = 0; nt < 8; nt++) {
            mx[0] = fmaxf(mx[0], fmaxf(accS[nt][0], accS[nt][1]));
            mx[1] = fmaxf(mx[1], fmaxf(accS[nt][2], accS[nt][3]));
        }
#pragma unroll
        for (int o = 1; o <= 2; o <<= 1) {
            mx[0] = fmaxf(mx[0], __shfl_xor_sync(0xffffffffu, mx[0], o));
            mx[1] = fmaxf(mx[1], __shfl_xor_sync(0xffffffffu, mx[1], o));
        }
        float fct[2], mnew[2], rsum[2] = {0.f, 0.f};
#pragma unroll
        for (int r2 = 0; r2 < 2; r2++) {
            mnew[r2] = fmaxf(mprev[r2], mx[r2]);
            fct[r2]  = ex2(mprev[r2] - mnew[r2]);
            mprev[r2] = mnew[r2];
        }
#pragma unroll
        for (int nt = 0; nt < 8; nt++)
#pragma unroll
            for (int r = 0; r < 4; r++) {
                float p = ex2(accS[nt][r] - mnew[r >> 1]);
                accS[nt][r] = p;
                rsum[r >> 1] += p;
            }
#pragma unroll
        for (int o = 1; o <= 2; o <<= 1) {
            rsum[0] += __shfl_xor_sync(0xffffffffu, rsum[0], o);
            rsum[1] += __shfl_xor_sync(0xffffffffu, rsum[1], o);
        }
        lsum[0] = lsum[0] * fct[0] + rsum[0];
        lsum[1] = lsum[1] * fct[1] + rsum[1];
#pragma unroll
        for (int nt = 0; nt < 8; nt++)
#pragma unroll
            for (int r = 0; r < 4; r++) accO[nt][r] *= fct[r >> 1];

#pragma unroll
        for (int kc = 0; kc < 4; kc++) {
            uint32_t ap[4];
            ap[0] = packh(accS[2 * kc][0],     accS[2 * kc][1]);
            ap[1] = packh(accS[2 * kc][2],     accS[2 * kc][3]);
            ap[2] = packh(accS[2 * kc + 1][0], accS[2 * kc + 1][1]);
            ap[3] = packh(accS[2 * kc + 1][2], accS[2 * kc + 1][3]);

            uint32_t vf[4][4];
#pragma unroll
            for (int p = 0; p < 4; p++) {
                int q = lane >> 3;
                int d = p * 16 + ((q >> 1) << 3) + (lane & 7);
                int c = kc * 2 + (q & 1);
                uint32_t off = d * 128 + ((c ^ (d & 7)) << 4);
                ldsm4(vf[p], kvb + 8192 + off);
            }
#pragma unroll
            for (int nt = 0; nt < 8; nt++)
                mma_f16(accO[nt], ap, &vf[nt >> 1][(nt & 1) * 2]);
        }
    }

    const float inv[2] = {1.0f / lsum[0], 1.0f / lsum[1]};
#pragma unroll
    for (int nt = 0; nt < 8; nt++) {
        int d0 = nt * 8 + 2 * t;
#pragma unroll
        for (int rp = 0; rp < 2; rp++) {
            int qrow = q0 + wid * 16 + g + rp * 8;
            float v0 = accO[nt][rp * 2 + 0] * inv[rp];
            float v1 = accO[nt][rp * 2 + 1] * inv[rp];
            size_t o = ((size_t)(b * Lq + qrow)) * Hdim + h * HD + d0;
            split_store2(g_ATTh + o, g_ATTl + o, v0, v1);
        }
    }
}

// ---------------- residual + LayerNorm ---------------------------------------
__global__ __launch_bounds__(256) void ln_k(const float* __restrict__ X,
                                            const float* __restrict__ gamma,
                                            const float* __restrict__ beta,
                                            float* __restrict__ out)
{
    __shared__ float buf[Hdim];
    __shared__ float rs[8], rss[8], stats[2];
    const int m = blockIdx.x;
    const int tid = threadIdx.x;
    const int lane = tid & 31, wid = tid >> 5;

    float s = 0.f, ss = 0.f;
#pragma unroll
    for (int i = 0; i < 4; i++) {
        int hh = i * 256 + tid;
        float v = g_O[(size_t)m * Hdim + hh] + X[(size_t)m * Hdim + hh];
        buf[hh] = v;
        s += v; ss += v * v;
    }
#pragma unroll
    for (int o = 16; o > 0; o >>= 1) {
        s  += __shfl_xor_sync(0xffffffffu, s, o);
        ss += __shfl_xor_sync(0xffffffffu, ss, o);
    }
    if (lane == 0) { rs[wid] = s; rss[wid] = ss; }
    __syncthreads();
    if (tid == 0) {
        float S = 0.f, SS = 0.f;
#pragma unroll
        for (int i = 0; i < 8; i++) { S += rs[i]; SS += rss[i]; }
        float mu = S * (1.0f / Hdim);
        stats[0] = mu;
        stats[1] = rsqrtf(SS * (1.0f / Hdim) - mu * mu + 1e-12f);
    }
    __syncthreads();
    float mu = stats[0], r = stats[1];
#pragma unroll
    for (int i = 0; i < 4; i++) {
        int hh = i * 256 + tid;
        out[(size_t)m * Hdim + hh] = (buf[hh] - mu) * r * gamma[hh] + beta[hh];
    }
}

// ---------------- launch ------------------------------------------------------
extern "C" void kernel_launch(void* const* d_in, const int* in_sizes, int n_in,
                              void* d_out, int out_size)
{
    const float* X     = (const float*)d_in[0];
    const float* mask  = (const float*)d_in[1];
    const float* Wq    = (const float*)d_in[2];
    const float* bq    = (const float*)d_in[3];
    const float* Wk    = (const float*)d_in[4];
    const float* bk    = (const float*)d_in[5];
    const float* Wv    = (const float*)d_in[6];
    const float* bv    = (const float*)d_in[7];
    const float* Wo    = (const float*)d_in[8];
    const float* bo    = (const float*)d_in[9];
    const float* gamma = (const float*)d_in[10];
    const float* beta  = (const float*)d_in[11];

    cudaFuncSetAttribute(gemm_qkv, cudaFuncAttributeMaxDynamicSharedMemorySize,
                         QKV_SMEM_BYTES);
    cudaFuncSetAttribute(gemm_o, cudaFuncAttributeMaxDynamicSharedMemorySize,
                         GEMM_SMEM_BYTES);
    cudaFuncSetAttribute(attn_k, cudaFuncAttributeMaxDynamicSharedMemorySize,
                         ATTN_SMEM_BYTES);

    split_x<<<(MROWS * Hdim) / 1024, 256>>>(X);
    split_w<<<dim3(Hdim / 32, Hdim / 32, 4), 256>>>(Wq, Wk, Wv, Wo);

    // merged QKV projections, fp16 single-plane
    gemm_qkv<<<dim3(8, 32, 3), 256, QKV_SMEM_BYTES>>>(bq, bk, bv);

    attn_k<<<dim3(Lq / 128, NH, Bdim), 256, ATTN_SMEM_BYTES>>>(mask);

    gemm_o<<<dim3(8, 32), 256, GEMM_SMEM_BYTES>>>(bo);

    ln_k<<<MROWS, 256>>>(X, gamma, beta, (float*)d_out);
}

// round 16
// speedup vs baseline: 10.0790x; 1.2042x over previous
#include <cuda_runtime.h>
#include <cuda_fp16.h>
#include <cstdint>

#define Bdim 2
#define Lq 2048
#define Hdim 1024
#define NH 16
#define HD 64
#define MROWS (Bdim * Lq)   // 4096
#define HH (Hdim * Hdim)

// ---------------- scratch (static device arrays; no allocation) --------------
__device__ __half g_Xf[(size_t)MROWS * Hdim];   // fp16 activations
__device__ __half g_Wf[(size_t)4 * HH];         // fp16 [n][k]: Wq,Wk,Wv,Wo
__device__ __half g_Qf[(size_t)MROWS * Hdim];   // [bh][l][d] fp16
__device__ __half g_Kf[(size_t)MROWS * Hdim];   // keys (= V-proj), [bh][l][d]
__device__ __half g_Vf[(size_t)MROWS * Hdim];   // values (= K-proj), [bh][d][l]
__device__ __half g_ATTf[(size_t)MROWS * Hdim]; // [b*l][h*64+d]
__device__ float  g_O[(size_t)MROWS * Hdim];

// ---------------- PTX helpers -------------------------------------------------
__device__ __forceinline__ uint32_t smem_u32(const void* p) {
    uint32_t a;
    asm("{ .reg .u64 t; cvta.to.shared.u64 t, %1; cvt.u32.u64 %0, t; }"
        : "=r"(a) : "l"(p));
    return a;
}
__device__ __forceinline__ void cpa16(uint32_t s, const void* g) {
    asm volatile("cp.async.cg.shared.global [%0], [%1], 16;" :: "r"(s), "l"(g));
}
#define CP_COMMIT() asm volatile("cp.async.commit_group;" ::: "memory")
#define CP_WAIT(n)  asm volatile("cp.async.wait_group %0;" :: "n"(n) : "memory")

__device__ __forceinline__ void ldsm4(uint32_t* r, uint32_t a) {
    asm volatile("ldmatrix.sync.aligned.m8n8.x4.shared.b16 {%0,%1,%2,%3}, [%4];"
                 : "=r"(r[0]), "=r"(r[1]), "=r"(r[2]), "=r"(r[3]) : "r"(a));
}
__device__ __forceinline__ void mma_f16(float* c, const uint32_t* a, const uint32_t* b) {
    asm volatile(
        "mma.sync.aligned.m16n8k16.row.col.f32.f16.f16.f32 "
        "{%0,%1,%2,%3}, {%4,%5,%6,%7}, {%8,%9}, {%0,%1,%2,%3};\n"
        : "+f"(c[0]), "+f"(c[1]), "+f"(c[2]), "+f"(c[3])
        : "r"(a[0]), "r"(a[1]), "r"(a[2]), "r"(a[3]), "r"(b[0]), "r"(b[1]));
}
__device__ __forceinline__ float ex2(float x) {
    float y;
    asm("ex2.approx.f32 %0, %1;" : "=f"(y) : "f"(x));
    return y;
}
__device__ __forceinline__ uint32_t packh(float a, float b) {
    __half2 h = __floats2half2_rn(a, b);
    return *(uint32_t*)&h;
}

// ---------------- preprocessing -----------------------------------------------
__global__ __launch_bounds__(256) void split_x(const float* __restrict__ x) {
    int e = (blockIdx.x * 256 + threadIdx.x) * 4;
    float4 v = *(const float4*)(x + e);
    *(__half2*)(g_Xf + e)     = __floats2half2_rn(v.x, v.y);
    *(__half2*)(g_Xf + e + 2) = __floats2half2_rn(v.z, v.w);
}

// transpose all weights to fp16 [n][k]
__global__ __launch_bounds__(256) void split_w(const float* __restrict__ W0,
                                               const float* __restrict__ W1,
                                               const float* __restrict__ W2,
                                               const float* __restrict__ W3) {
    __shared__ float tb[32][33];
    const int w = blockIdx.z;
    const float* src = (w == 0) ? W0 : (w == 1) ? W1 : (w == 2) ? W2 : W3;
    const int k0 = blockIdx.x * 32, n0 = blockIdx.y * 32;
    const int tx = threadIdx.x & 31, ty = threadIdx.x >> 5;  // 32 x 8
#pragma unroll
    for (int i = 0; i < 4; i++) {
        int r = ty + i * 8;
        tb[r][tx] = src[(size_t)(k0 + r) * Hdim + n0 + tx];   // read [k][n]
    }
    __syncthreads();
    __half* d = g_Wf + (size_t)w * HH;
#pragma unroll
    for (int i = 0; i < 4; i++) {
        int r = ty + i * 8;
        d[(size_t)(n0 + r) * Hdim + k0 + tx] = __float2half_rn(tb[tx][r]);
    }
}

// ============ GEMM: 128x128x(BK=64) fp16 single-plane, 3-stage ================
// smem per stage: A 16K | B 16K = 32KB; 3 stages = 96KB
#define GEMM_SMEM_BYTES (96 * 1024)
#define NKT2 16   // 1024 / 64

__global__ __launch_bounds__(256) void gemm_f16(const float* __restrict__ b0,
                                                const float* __restrict__ b1,
                                                const float* __restrict__ b2,
                                                const float* __restrict__ b3,
                                                int base)
{
    extern __shared__ char smc[];
    const uint32_t sb = smem_u32(smc);
    const int which = base + blockIdx.z;
    const float* __restrict__ bias =
        (which == 0) ? b0 : (which == 1) ? b1 : (which == 2) ? b2 : b3;

    const int tid = threadIdx.x;
    const int wid = tid >> 5, lane = tid & 31;
    const int g = lane >> 2, t = lane & 3;
    const int wm = wid & 3, wn = wid >> 2;            // 4x2 warps, tile 32m x 64n
    const int row0 = blockIdx.y * 128, col0 = blockIdx.x * 128;

    const __half* __restrict__ Aa = (which == 3) ? g_ATTf : g_Xf;
    const __half* __restrict__ Bw = g_Wf + (size_t)which * HH;

    float acc[2][8][4];
#pragma unroll
    for (int i = 0; i < 2; i++)
#pragma unroll
        for (int j = 0; j < 8; j++)
#pragma unroll
            for (int r = 0; r < 4; r++) acc[i][j][r] = 0.f;

    auto stage = [&](int kt, int s) {
        const uint32_t ab = sb + s * 32768;
#pragma unroll
        for (int i = 0; i < 4; i++) {
            int e = tid + i * 256;           // 1024: A 128 rows x 8 chunks
            int m = e >> 3, c = e & 7;
            uint32_t off = m * 128 + ((c ^ (m & 7)) << 4);
            cpa16(ab + off, Aa + (size_t)(row0 + m) * Hdim + kt * 64 + c * 8);
        }
#pragma unroll
        for (int i = 0; i < 4; i++) {
            int e = tid + i * 256;           // 1024: B 128 rows x 8 chunks
            int n = e >> 3, c = e & 7;
            uint32_t off = n * 128 + ((c ^ (n & 7)) << 4);
            cpa16(ab + 16384 + off, Bw + (size_t)(col0 + n) * Hdim + kt * 64 + c * 8);
        }
        CP_COMMIT();
    };

    stage(0, 0);
    stage(1, 1);
    for (int kt = 0; kt < NKT2; kt++) {
        const int s = kt % 3;
        if (kt + 1 < NKT2) CP_WAIT(1);
        else               CP_WAIT(0);
        __syncthreads();
        if (kt + 2 < NKT2) stage(kt + 2, (kt + 2) % 3);

        const uint32_t ab = sb + s * 32768;
#pragma unroll
        for (int kc = 0; kc < 4; kc++) {
            uint32_t af[2][4];
#pragma unroll
            for (int mt = 0; mt < 2; mt++) {
                int m = wm * 32 + mt * 16 + (lane & 7) + ((lane >> 3) & 1) * 8;
                int c = kc * 2 + (lane >> 4);
                uint32_t off = m * 128 + ((c ^ (m & 7)) << 4);
                ldsm4(af[mt], ab + off);
            }
            uint32_t bf[4][4];
#pragma unroll
            for (int p = 0; p < 4; p++) {
                int q = lane >> 3;
                int n = wn * 64 + p * 16 + (lane & 7) + ((q >> 1) << 3);
                int c = kc * 2 + (q & 1);
                uint32_t off = n * 128 + ((c ^ (n & 7)) << 4);
                ldsm4(bf[p], ab + 16384 + off);
            }
#pragma unroll
            for (int nt = 0; nt < 8; nt++)
#pragma unroll
                for (int mt = 0; mt < 2; mt++)
                    mma_f16(acc[mt][nt], af[mt], &bf[nt >> 1][(nt & 1) * 2]);
        }
    }

    // epilogue: bias + route
#pragma unroll
    for (int mt = 0; mt < 2; mt++)
#pragma unroll
        for (int nt = 0; nt < 8; nt++) {
            int colb = col0 + wn * 64 + nt * 8 + 2 * t;
            float bb0 = bias[colb], bb1 = bias[colb + 1];
#pragma unroll
            for (int rp = 0; rp < 2; rp++) {
                int row = row0 + wm * 32 + mt * 16 + g + rp * 8;
                float v0 = acc[mt][nt][rp * 2 + 0] + bb0;
                float v1 = acc[mt][nt][rp * 2 + 1] + bb1;
                int bb = row >> 11, l = row & (Lq - 1);
                int h = colb >> 6, d = colb & 63;
                if (which == 0) {
                    size_t o = (((size_t)(bb * NH + h)) * Lq + l) * HD + d;
                    *(__half2*)(g_Qf + o) = __floats2half2_rn(v0, v1);
                } else if (which == 2) {
                    size_t o = (((size_t)(bb * NH + h)) * Lq + l) * HD + d;
                    *(__half2*)(g_Kf + o) = __floats2half2_rn(v0, v1);
                } else if (which == 1) {
                    size_t o = ((size_t)(bb * NH + h) * HD + d) * Lq + l;
                    g_Vf[o]      = __float2half_rn(v0);
                    g_Vf[o + Lq] = __float2half_rn(v1);
                } else {
                    float2 v; v.x = v0; v.y = v1;
                    *(float2*)(g_O + (size_t)row * Hdim + colb) = v;
                }
            }
        }
}

// ============ Flash attention, fp16 single-plane (keys=V-proj, values=K-proj) =
// energies = Q @ keys^T / 4 + mask; attended = softmax @ values
// smem: Q 16K | 3 x { K 8K | V 8K } | 3 x mask 256B = 66304 B
#define NKB (Lq / 64)
#define ATTN_SMEM_BYTES 66304

__global__ __launch_bounds__(256, 2) void attn_k(const float* __restrict__ mask)
{
    extern __shared__ char smc[];
    const uint32_t sb = smem_u32(smc);
    const int tid = threadIdx.x;
    const int wid = tid >> 5, lane = tid & 31;
    const int g = lane >> 2, t = lane & 3;
    const int q0 = blockIdx.x * 128;
    const int h = blockIdx.y, b = blockIdx.z;
    const int bh = b * NH + h;
    const float* __restrict__ maskp = mask + (size_t)b * Lq;

    const float LOG2E = 1.4426950408889634f;
    const float C025  = 0.25f * LOG2E;

#pragma unroll
    for (int i = 0; i < 4; i++) {
        int e = tid + i * 256;
        int q = e >> 3, c = e & 7;
        uint32_t off = q * 128 + ((c ^ (q & 7)) << 4);
        cpa16(sb + off, g_Qf + (size_t)((size_t)bh * Lq + q0 + q) * HD + c * 8);
    }
    CP_COMMIT();

    auto stageKV = [&](int kb, int s) {
        const int k0 = kb * 64;
        const uint32_t kvb = sb + 16384 + s * 16384;
#pragma unroll
        for (int i = 0; i < 2; i++) {
            int e = tid + i * 256;
            int row = e >> 3, c = e & 7;
            uint32_t off = row * 128 + ((c ^ (row & 7)) << 4);
            cpa16(kvb + off,
                  g_Kf + (size_t)((size_t)bh * Lq + k0 + row) * HD + c * 8);
            cpa16(kvb + 8192 + off,
                  g_Vf + ((size_t)bh * HD + row) * Lq + k0 + c * 8);
        }
        if (tid < 16) cpa16(sb + 65536 + s * 256 + tid * 16, maskp + k0 + tid * 4);
        CP_COMMIT();
    };

    stageKV(0, 0);
    stageKV(1, 1);

    uint32_t qf[4][4];
    float mprev[2] = {-1e30f, -1e30f};
    float lsum[2]  = {0.f, 0.f};
    float accO[8][4];
#pragma unroll
    for (int nt = 0; nt < 8; nt++)
#pragma unroll
        for (int r = 0; r < 4; r++) accO[nt][r] = 0.f;

    for (int kb = 0; kb < NKB; kb++) {
        const int s = kb % 3;
        if (kb + 1 < NKB) CP_WAIT(1);
        else              CP_WAIT(0);
        __syncthreads();
        if (kb + 2 < NKB) stageKV(kb + 2, (kb + 2) % 3);

        if (kb == 0) {
#pragma unroll
            for (int kc = 0; kc < 4; kc++) {
                int m = wid * 16 + (lane & 7) + ((lane >> 3) & 1) * 8;
                int c = kc * 2 + (lane >> 4);
                uint32_t off = m * 128 + ((c ^ (m & 7)) << 4);
                ldsm4(qf[kc], sb + off);
            }
        }

        const uint32_t kvb = sb + 16384 + s * 16384;

        float accS[8][4];
#pragma unroll
        for (int nt = 0; nt < 8; nt++)
#pragma unroll
            for (int r = 0; r < 4; r++) accS[nt][r] = 0.f;

#pragma unroll
        for (int kc = 0; kc < 4; kc++) {
            uint32_t kh[4][4];
#pragma unroll
            for (int p = 0; p < 4; p++) {
                int q = lane >> 3;
                int key = p * 16 + (lane & 7) + ((q >> 1) << 3);
                int c = kc * 2 + (q & 1);
                uint32_t off = key * 128 + ((c ^ (key & 7)) << 4);
                ldsm4(kh[p], kvb + off);
            }
#pragma unroll
            for (int nt = 0; nt < 8; nt++)
                mma_f16(accS[nt], qf[kc], &kh[nt >> 1][(nt & 1) * 2]);
        }

        const float* ms = (const float*)(smc + 65536 + s * 256);
#pragma unroll
        for (int nt = 0; nt < 8; nt++) {
            float m0 = ms[nt * 8 + 2 * t]     * LOG2E;
            float m1 = ms[nt * 8 + 2 * t + 1] * LOG2E;
#pragma unroll
            for (int r = 0; r < 4; r++)
                accS[nt][r] = accS[nt][r] * C025 + ((r & 1) ? m1 : m0);
        }

        float mx[2] = {-1e30f, -1e30f};
#pragma unroll
        for (int nt = 0; nt < 8; nt++) {
            mx[0] = fmaxf(mx[0], fmaxf(accS[nt][0], accS[nt][1]));
            mx[1] = fmaxf(mx[1], fmaxf(accS[nt][2], accS[nt][3]));
        }
#pragma unroll
        for (int o = 1; o <= 2; o <<= 1) {
            mx[0] = fmaxf(mx[0], __shfl_xor_sync(0xffffffffu, mx[0], o));
            mx[1] = fmaxf(mx[1], __shfl_xor_sync(0xffffffffu, mx[1], o));
        }
        float fct[2], mnew[2], rsum[2] = {0.f, 0.f};
#pragma unroll
        for (int r2 = 0; r2 < 2; r2++) {
            mnew[r2] = fmaxf(mprev[r2], mx[r2]);
            fct[r2]  = ex2(mprev[r2] - mnew[r2]);
            mprev[r2] = mnew[r2];
        }
#pragma unroll
        for (int nt = 0; nt < 8; nt++)
#pragma unroll
            for (int r = 0; r < 4; r++) {
                float p = ex2(accS[nt][r] - mnew[r >> 1]);
                accS[nt][r] = p;
                rsum[r >> 1] += p;
            }
#pragma unroll
        for (int o = 1; o <= 2; o <<= 1) {
            rsum[0] += __shfl_xor_sync(0xffffffffu, rsum[0], o);
            rsum[1] += __shfl_xor_sync(0xffffffffu, rsum[1], o);
        }
        lsum[0] = lsum[0] * fct[0] + rsum[0];
        lsum[1] = lsum[1] * fct[1] + rsum[1];
#pragma unroll
        for (int nt = 0; nt < 8; nt++)
#pragma unroll
            for (int r = 0; r < 4; r++) accO[nt][r] *= fct[r >> 1];

#pragma unroll
        for (int kc = 0; kc < 4; kc++) {
            uint32_t ap[4];
            ap[0] = packh(accS[2 * kc][0],     accS[2 * kc][1]);
            ap[1] = packh(accS[2 * kc][2],     accS[2 * kc][3]);
            ap[2] = packh(accS[2 * kc + 1][0], accS[2 * kc + 1][1]);
            ap[3] = packh(accS[2 * kc + 1][2], accS[2 * kc + 1][3]);

            uint32_t vf[4][4];
#pragma unroll
            for (int p = 0; p < 4; p++) {
                int q = lane >> 3;
                int d = p * 16 + ((q >> 1) << 3) + (lane & 7);
                int c = kc * 2 + (q & 1);
                uint32_t off = d * 128 + ((c ^ (d & 7)) << 4);
                ldsm4(vf[p], kvb + 8192 + off);
            }
#pragma unroll
            for (int nt = 0; nt < 8; nt++)
                mma_f16(accO[nt], ap, &vf[nt >> 1][(nt & 1) * 2]);
        }
    }

    // ---- normalize + write fp16 ATT ----
    const float inv[2] = {1.0f / lsum[0], 1.0f / lsum[1]};
#pragma unroll
    for (int nt = 0; nt < 8; nt++) {
        int d0 = nt * 8 + 2 * t;
#pragma unroll
        for (int rp = 0; rp < 2; rp++) {
            int qrow = q0 + wid * 16 + g + rp * 8;
            float v0 = accO[nt][rp * 2 + 0] * inv[rp];
            float v1 = accO[nt][rp * 2 + 1] * inv[rp];
            size_t o = ((size_t)(b * Lq + qrow)) * Hdim + h * HD + d0;
            *(__half2*)(g_ATTf + o) = __floats2half2_rn(v0, v1);
        }
    }
}

// ---------------- residual + LayerNorm ---------------------------------------
__global__ __launch_bounds__(256) void ln_k(const float* __restrict__ X,
                                            const float* __restrict__ gamma,
                                            const float* __restrict__ beta,
                                            float* __restrict__ out)
{
    __shared__ float buf[Hdim];
    __shared__ float rs[8], rss[8], stats[2];
    const int m = blockIdx.x;
    const int tid = threadIdx.x;
    const int lane = tid & 31, wid = tid >> 5;

    float s = 0.f, ss = 0.f;
#pragma unroll
    for (int i = 0; i < 4; i++) {
        int hh = i * 256 + tid;
        float v = g_O[(size_t)m * Hdim + hh] + X[(size_t)m * Hdim + hh];
        buf[hh] = v;
        s += v; ss += v * v;
    }
#pragma unroll
    for (int o = 16; o > 0; o >>= 1) {
        s  += __shfl_xor_sync(0xffffffffu, s, o);
        ss += __shfl_xor_sync(0xffffffffu, ss, o);
    }
    if (lane == 0) { rs[wid] = s; rss[wid] = ss; }
    __syncthreads();
    if (tid == 0) {
        float S = 0.f, SS = 0.f;
#pragma unroll
        for (int i = 0; i < 8; i++) { S += rs[i]; SS += rss[i]; }
        float mu = S * (1.0f / Hdim);
        stats[0] = mu;
        stats[1] = rsqrtf(SS * (1.0f / Hdim) - mu * mu + 1e-12f);
    }
    __syncthreads();
    float mu = stats[0], r = stats[1];
#pragma unroll
    for (int i = 0; i < 4; i++) {
        int hh = i * 256 + tid;
        out[(size_t)m * Hdim + hh] = (buf[hh] - mu) * r * gamma[hh] + beta[hh];
    }
}

// ---------------- launch ------------------------------------------------------
extern "C" void kernel_launch(void* const* d_in, const int* in_sizes, int n_in,
                              void* d_out, int out_size)
{
    const float* X     = (const float*)d_in[0];
    const float* mask  = (const float*)d_in[1];
    const float* Wq    = (const float*)d_in[2];
    const float* bq    = (const float*)d_in[3];
    const float* Wk    = (const float*)d_in[4];
    const float* bk    = (const float*)d_in[5];
    const float* Wv    = (const float*)d_in[6];
    const float* bv    = (const float*)d_in[7];
    const float* Wo    = (const float*)d_in[8];
    const float* bo    = (const float*)d_in[9];
    const float* gamma = (const float*)d_in[10];
    const float* beta  = (const float*)d_in[11];

    cudaFuncSetAttribute(gemm_f16, cudaFuncAttributeMaxDynamicSharedMemorySize,
                         GEMM_SMEM_BYTES);
    cudaFuncSetAttribute(attn_k, cudaFuncAttributeMaxDynamicSharedMemorySize,
                         ATTN_SMEM_BYTES);

    split_x<<<(MROWS * Hdim) / 1024, 256>>>(X);
    split_w<<<dim3(Hdim / 32, Hdim / 32, 4), 256>>>(Wq, Wk, Wv, Wo);

    // merged QKV projections, fp16 single-plane
    gemm_f16<<<dim3(8, 32, 3), 256, GEMM_SMEM_BYTES>>>(bq, bk, bv, bo, 0);

    attn_k<<<dim3(Lq / 128, NH, Bdim), 256, ATTN_SMEM_BYTES>>>(mask);

    // O-projection, fp16 single-plane
    gemm_f16<<<dim3(8, 32, 1), 256, GEMM_SMEM_BYTES>>>(bq, bk, bv, bo, 3);

    ln_k<<<MROWS, 256>>>(X, gamma, beta, (float*)d_out);
}

// round 17
// speedup vs baseline: 11.0168x; 1.0931x over previous
#include <cuda_runtime.h>
#include <cuda_fp16.h>
#include <cstdint>

#define Bdim 2
#define Lq 2048
#define Hdim 1024
#define NH 16
#define HD 64
#define MROWS (Bdim * Lq)   // 4096
#define HH (Hdim * Hdim)

// ---------------- scratch (static device arrays; no allocation) --------------
__device__ __half g_Xf[(size_t)MROWS * Hdim];   // fp16 activations
__device__ __half g_Wf[(size_t)4 * HH];         // fp16 [n][k]: Wq,Wk,Wv,Wo
__device__ __half g_Qf[(size_t)MROWS * Hdim];   // [bh][l][d] fp16
__device__ __half g_Kf[(size_t)MROWS * Hdim];   // keys (= V-proj), [bh][l][d]
__device__ __half g_Vf[(size_t)MROWS * Hdim];   // values (= K-proj), [bh][d][l]
__device__ __half g_ATTf[(size_t)MROWS * Hdim]; // [b*l][h*64+d]
__device__ float  g_O[(size_t)MROWS * Hdim];

// ---------------- PTX helpers -------------------------------------------------
__device__ __forceinline__ uint32_t smem_u32(const void* p) {
    uint32_t a;
    asm("{ .reg .u64 t; cvta.to.shared.u64 t, %1; cvt.u32.u64 %0, t; }"
        : "=r"(a) : "l"(p));
    return a;
}
__device__ __forceinline__ void cpa16(uint32_t s, const void* g) {
    asm volatile("cp.async.cg.shared.global [%0], [%1], 16;" :: "r"(s), "l"(g));
}
#define CP_COMMIT() asm volatile("cp.async.commit_group;" ::: "memory")
#define CP_WAIT(n)  asm volatile("cp.async.wait_group %0;" :: "n"(n) : "memory")

__device__ __forceinline__ void ldsm4(uint32_t* r, uint32_t a) {
    asm volatile("ldmatrix.sync.aligned.m8n8.x4.shared.b16 {%0,%1,%2,%3}, [%4];"
                 : "=r"(r[0]), "=r"(r[1]), "=r"(r[2]), "=r"(r[3]) : "r"(a));
}
__device__ __forceinline__ void mma_f16(float* c, const uint32_t* a, const uint32_t* b) {
    asm volatile(
        "mma.sync.aligned.m16n8k16.row.col.f32.f16.f16.f32 "
        "{%0,%1,%2,%3}, {%4,%5,%6,%7}, {%8,%9}, {%0,%1,%2,%3};\n"
        : "+f"(c[0]), "+f"(c[1]), "+f"(c[2]), "+f"(c[3])
        : "r"(a[0]), "r"(a[1]), "r"(a[2]), "r"(a[3]), "r"(b[0]), "r"(b[1]));
}
__device__ __forceinline__ float ex2(float x) {
    float y;
    asm("ex2.approx.f32 %0, %1;" : "=f"(y) : "f"(x));
    return y;
}
__device__ __forceinline__ __half2 ex2h2(__half2 x) {
    uint32_t xi = *(uint32_t*)&x, yi;
    asm("ex2.approx.f16x2 %0, %1;" : "=r"(yi) : "r"(xi));
    return *(__half2*)&yi;
}
__device__ __forceinline__ uint32_t h2u(__half2 h) { return *(uint32_t*)&h; }

// ---------------- preprocessing -----------------------------------------------
__global__ __launch_bounds__(256) void split_x(const float* __restrict__ x) {
    int e = (blockIdx.x * 256 + threadIdx.x) * 4;
    float4 v = *(const float4*)(x + e);
    *(__half2*)(g_Xf + e)     = __floats2half2_rn(v.x, v.y);
    *(__half2*)(g_Xf + e + 2) = __floats2half2_rn(v.z, v.w);
}

// transpose all weights to fp16 [n][k]
__global__ __launch_bounds__(256) void split_w(const float* __restrict__ W0,
                                               const float* __restrict__ W1,
                                               const float* __restrict__ W2,
                                               const float* __restrict__ W3) {
    __shared__ float tb[32][33];
    const int w = blockIdx.z;
    const float* src = (w == 0) ? W0 : (w == 1) ? W1 : (w == 2) ? W2 : W3;
    const int k0 = blockIdx.x * 32, n0 = blockIdx.y * 32;
    const int tx = threadIdx.x & 31, ty = threadIdx.x >> 5;  // 32 x 8
#pragma unroll
    for (int i = 0; i < 4; i++) {
        int r = ty + i * 8;
        tb[r][tx] = src[(size_t)(k0 + r) * Hdim + n0 + tx];   // read [k][n]
    }
    __syncthreads();
    __half* d = g_Wf + (size_t)w * HH;
#pragma unroll
    for (int i = 0; i < 4; i++) {
        int r = ty + i * 8;
        d[(size_t)(n0 + r) * Hdim + k0 + tx] = __float2half_rn(tb[tx][r]);
    }
}

// ============ GEMM: 128x128x(BK=64) fp16 single-plane, 3-stage ================
// smem per stage: A 16K | B 16K = 32KB; 3 stages = 96KB
#define GEMM_SMEM_BYTES (96 * 1024)
#define NKT2 16   // 1024 / 64

__global__ __launch_bounds__(256) void gemm_f16(const float* __restrict__ b0,
                                                const float* __restrict__ b1,
                                                const float* __restrict__ b2,
                                                const float* __restrict__ b3,
                                                int base)
{
    extern __shared__ char smc[];
    const uint32_t sb = smem_u32(smc);
    const int which = base + blockIdx.z;
    const float* __restrict__ bias =
        (which == 0) ? b0 : (which == 1) ? b1 : (which == 2) ? b2 : b3;

    const int tid = threadIdx.x;
    const int wid = tid >> 5, lane = tid & 31;
    const int g = lane >> 2, t = lane & 3;
    const int wm = wid & 3, wn = wid >> 2;            // 4x2 warps, tile 32m x 64n
    const int row0 = blockIdx.y * 128, col0 = blockIdx.x * 128;

    const __half* __restrict__ Aa = (which == 3) ? g_ATTf : g_Xf;
    const __half* __restrict__ Bw = g_Wf + (size_t)which * HH;

    float acc[2][8][4];
#pragma unroll
    for (int i = 0; i < 2; i++)
#pragma unroll
        for (int j = 0; j < 8; j++)
#pragma unroll
            for (int r = 0; r < 4; r++) acc[i][j][r] = 0.f;

    auto stage = [&](int kt, int s) {
        const uint32_t ab = sb + s * 32768;
#pragma unroll
        for (int i = 0; i < 4; i++) {
            int e = tid + i * 256;           // 1024: A 128 rows x 8 chunks
            int m = e >> 3, c = e & 7;
            uint32_t off = m * 128 + ((c ^ (m & 7)) << 4);
            cpa16(ab + off, Aa + (size_t)(row0 + m) * Hdim + kt * 64 + c * 8);
        }
#pragma unroll
        for (int i = 0; i < 4; i++) {
            int e = tid + i * 256;           // 1024: B 128 rows x 8 chunks
            int n = e >> 3, c = e & 7;
            uint32_t off = n * 128 + ((c ^ (n & 7)) << 4);
            cpa16(ab + 16384 + off, Bw + (size_t)(col0 + n) * Hdim + kt * 64 + c * 8);
        }
        CP_COMMIT();
    };

    stage(0, 0);
    stage(1, 1);
    for (int kt = 0; kt < NKT2; kt++) {
        const int s = kt % 3;
        if (kt + 1 < NKT2) CP_WAIT(1);
        else               CP_WAIT(0);
        __syncthreads();
        if (kt + 2 < NKT2) stage(kt + 2, (kt + 2) % 3);

        const uint32_t ab = sb + s * 32768;
#pragma unroll
        for (int kc = 0; kc < 4; kc++) {
            uint32_t af[2][4];
#pragma unroll
            for (int mt = 0; mt < 2; mt++) {
                int m = wm * 32 + mt * 16 + (lane & 7) + ((lane >> 3) & 1) * 8;
                int c = kc * 2 + (lane >> 4);
                uint32_t off = m * 128 + ((c ^ (m & 7)) << 4);
                ldsm4(af[mt], ab + off);
            }
            uint32_t bf[4][4];
#pragma unroll
            for (int p = 0; p < 4; p++) {
                int q = lane >> 3;
                int n = wn * 64 + p * 16 + (lane & 7) + ((q >> 1) << 3);
                int c = kc * 2 + (q & 1);
                uint32_t off = n * 128 + ((c ^ (n & 7)) << 4);
                ldsm4(bf[p], ab + 16384 + off);
            }
#pragma unroll
            for (int nt = 0; nt < 8; nt++)
#pragma unroll
                for (int mt = 0; mt < 2; mt++)
                    mma_f16(acc[mt][nt], af[mt], &bf[nt >> 1][(nt & 1) * 2]);
        }
    }

    // epilogue: bias + route
#pragma unroll
    for (int mt = 0; mt < 2; mt++)
#pragma unroll
        for (int nt = 0; nt < 8; nt++) {
            int colb = col0 + wn * 64 + nt * 8 + 2 * t;
            float bb0 = bias[colb], bb1 = bias[colb + 1];
#pragma unroll
            for (int rp = 0; rp < 2; rp++) {
                int row = row0 + wm * 32 + mt * 16 + g + rp * 8;
                float v0 = acc[mt][nt][rp * 2 + 0] + bb0;
                float v1 = acc[mt][nt][rp * 2 + 1] + bb1;
                int bb = row >> 11, l = row & (Lq - 1);
                int h = colb >> 6, d = colb & 63;
                if (which == 0) {
                    size_t o = (((size_t)(bb * NH + h)) * Lq + l) * HD + d;
                    *(__half2*)(g_Qf + o) = __floats2half2_rn(v0, v1);
                } else if (which == 2) {
                    size_t o = (((size_t)(bb * NH + h)) * Lq + l) * HD + d;
                    *(__half2*)(g_Kf + o) = __floats2half2_rn(v0, v1);
                } else if (which == 1) {
                    size_t o = ((size_t)(bb * NH + h) * HD + d) * Lq + l;
                    g_Vf[o]      = __float2half_rn(v0);
                    g_Vf[o + Lq] = __float2half_rn(v1);
                } else {
                    float2 v; v.x = v0; v.y = v1;
                    *(float2*)(g_O + (size_t)row * Hdim + colb) = v;
                }
            }
        }
}

// ============ Flash attention, fp16, f16x2 softmax, ones-column lsum ==========
// energies = Q @ keys^T / 4 + mask; attended = softmax @ values
// smem: Q 16K | 4 x { K 8K | V 8K } | 4 x mask 256B = 82944 B
#define NKB (Lq / 64)
#define ATTN_SMEM_BYTES 82944

__global__ __launch_bounds__(256, 2) void attn_k(const float* __restrict__ mask)
{
    extern __shared__ char smc[];
    const uint32_t sb = smem_u32(smc);
    const int tid = threadIdx.x;
    const int wid = tid >> 5, lane = tid & 31;
    const int g = lane >> 2, t = lane & 3;
    const int q0 = blockIdx.x * 128;
    const int h = blockIdx.y, b = blockIdx.z;
    const int bh = b * NH + h;
    const float* __restrict__ maskp = mask + (size_t)b * Lq;

    const float LOG2E = 1.4426950408889634f;
    const float C025  = 0.25f * LOG2E;

#pragma unroll
    for (int i = 0; i < 4; i++) {
        int e = tid + i * 256;
        int q = e >> 3, c = e & 7;
        uint32_t off = q * 128 + ((c ^ (q & 7)) << 4);
        cpa16(sb + off, g_Qf + (size_t)((size_t)bh * Lq + q0 + q) * HD + c * 8);
    }
    CP_COMMIT();

    auto stageKV = [&](int kb, int s) {
        const int k0 = kb * 64;
        const uint32_t kvb = sb + 16384 + s * 16384;
#pragma unroll
        for (int i = 0; i < 2; i++) {
            int e = tid + i * 256;
            int row = e >> 3, c = e & 7;
            uint32_t off = row * 128 + ((c ^ (row & 7)) << 4);
            cpa16(kvb + off,
                  g_Kf + (size_t)((size_t)bh * Lq + k0 + row) * HD + c * 8);
            cpa16(kvb + 8192 + off,
                  g_Vf + ((size_t)bh * HD + row) * Lq + k0 + c * 8);
        }
        if (tid < 16) cpa16(sb + 81920 + s * 256 + tid * 16, maskp + k0 + tid * 4);
        CP_COMMIT();
    };

    stageKV(0, 0);
    stageKV(1, 1);
    stageKV(2, 2);

    uint32_t qf[4][4];
    __half2 mprev2 = __floats2half2_rn(-60000.f, -60000.f);   // (row g, row g+8)
    float accO[9][4];   // [8] = ones-column row sums
#pragma unroll
    for (int nt = 0; nt < 9; nt++)
#pragma unroll
        for (int r = 0; r < 4; r++) accO[nt][r] = 0.f;
    const uint32_t ones_b[2] = {0x3C003C00u, 0x3C003C00u};

    for (int kb = 0; kb < NKB; kb++) {
        const int s = kb & 3;
        if (kb < NKB - 3) CP_WAIT(2);
        else              CP_WAIT(0);
        __syncthreads();
        if (kb + 3 < NKB) stageKV(kb + 3, (kb + 3) & 3);

        if (kb == 0) {
#pragma unroll
            for (int kc = 0; kc < 4; kc++) {
                int m = wid * 16 + (lane & 7) + ((lane >> 3) & 1) * 8;
                int c = kc * 2 + (lane >> 4);
                uint32_t off = m * 128 + ((c ^ (m & 7)) << 4);
                ldsm4(qf[kc], sb + off);
            }
        }

        const uint32_t kvb = sb + 16384 + s * 16384;

        // ---- S = Q @ keys^T (fp16, k over d=64) ----
        float accS[8][4];
#pragma unroll
        for (int nt = 0; nt < 8; nt++)
#pragma unroll
            for (int r = 0; r < 4; r++) accS[nt][r] = 0.f;

#pragma unroll
        for (int kc = 0; kc < 4; kc++) {
            uint32_t kh[4][4];
#pragma unroll
            for (int p = 0; p < 4; p++) {
                int q = lane >> 3;
                int key = p * 16 + (lane & 7) + ((q >> 1) << 3);
                int c = kc * 2 + (q & 1);
                uint32_t off = key * 128 + ((c ^ (key & 7)) << 4);
                ldsm4(kh[p], kvb + off);
            }
#pragma unroll
            for (int nt = 0; nt < 8; nt++)
                mma_f16(accS[nt], qf[kc], &kh[nt >> 1][(nt & 1) * 2]);
        }

        // ---- scale + mask (log2 domain), pack to half2 ----
        const float* ms = (const float*)(smc + 81920 + s * 256);
        __half2 h01[8], h23[8];
#pragma unroll
        for (int nt = 0; nt < 8; nt++) {
            float m0 = ms[nt * 8 + 2 * t]     * LOG2E;
            float m1 = ms[nt * 8 + 2 * t + 1] * LOG2E;
            h01[nt] = __floats2half2_rn(accS[nt][0] * C025 + m0,
                                        accS[nt][1] * C025 + m1);
            h23[nt] = __floats2half2_rn(accS[nt][2] * C025 + m0,
                                        accS[nt][3] * C025 + m1);
        }

        // ---- row max (hmax2 tree + packed quad shfl) ----
        __half2 p01 = __hmax2(__hmax2(__hmax2(h01[0], h01[1]), __hmax2(h01[2], h01[3])),
                              __hmax2(__hmax2(h01[4], h01[5]), __hmax2(h01[6], h01[7])));
        __half2 p23 = __hmax2(__hmax2(__hmax2(h23[0], h23[1]), __hmax2(h23[2], h23[3])),
                              __hmax2(__hmax2(h23[4], h23[5]), __hmax2(h23[6], h23[7])));
        __half2 rowmax = __halves2half2(__hmax(__low2half(p01), __high2half(p01)),
                                        __hmax(__low2half(p23), __high2half(p23)));
#pragma unroll
        for (int o = 1; o <= 2; o <<= 1) {
            uint32_t other = __shfl_xor_sync(0xffffffffu, h2u(rowmax), o);
            rowmax = __hmax2(rowmax, *(__half2*)&other);
        }
        __half2 mnew2 = __hmax2(rowmax, mprev2);
        float fct0 = ex2(__half2float(__low2half(mprev2))  - __half2float(__low2half(mnew2)));
        float fct1 = ex2(__half2float(__high2half(mprev2)) - __half2float(__high2half(mnew2)));
        mprev2 = mnew2;
        __half2 bg = __half2half2(__low2half(mnew2));
        __half2 b8 = __half2half2(__high2half(mnew2));

        // ---- P = exp2(S - mnew) in f16x2 (these ARE the PV A-fragments) ----
#pragma unroll
        for (int nt = 0; nt < 8; nt++) {
            h01[nt] = ex2h2(__hsub2(h01[nt], bg));
            h23[nt] = ex2h2(__hsub2(h23[nt], b8));
        }

        // ---- rescale accO (incl. ones column) ----
#pragma unroll
        for (int nt = 0; nt < 9; nt++) {
            accO[nt][0] *= fct0; accO[nt][1] *= fct0;
            accO[nt][2] *= fct1; accO[nt][3] *= fct1;
        }

        // ---- O += P @ values; ones-column mma accumulates row sums ----
#pragma unroll
        for (int kc = 0; kc < 4; kc++) {
            uint32_t ap[4];
            ap[0] = h2u(h01[2 * kc]);
            ap[1] = h2u(h23[2 * kc]);
            ap[2] = h2u(h01[2 * kc + 1]);
            ap[3] = h2u(h23[2 * kc + 1]);

            uint32_t vf[4][4];
#pragma unroll
            for (int p = 0; p < 4; p++) {
                int q = lane >> 3;
                int d = p * 16 + ((q >> 1) << 3) + (lane & 7);
                int c = kc * 2 + (q & 1);
                uint32_t off = d * 128 + ((c ^ (d & 7)) << 4);
                ldsm4(vf[p], kvb + 8192 + off);
            }
#pragma unroll
            for (int nt = 0; nt < 8; nt++)
                mma_f16(accO[nt], ap, &vf[nt >> 1][(nt & 1) * 2]);
            mma_f16(accO[8], ap, ones_b);
        }
    }

    // ---- normalize (lsum = ones column) + write fp16 ATT ----
    const float inv[2] = {1.0f / accO[8][0], 1.0f / accO[8][2]};
#pragma unroll
    for (int nt = 0; nt < 8; nt++) {
        int d0 = nt * 8 + 2 * t;
#pragma unroll
        for (int rp = 0; rp < 2; rp++) {
            int qrow = q0 + wid * 16 + g + rp * 8;
            float v0 = accO[nt][rp * 2 + 0] * inv[rp];
            float v1 = accO[nt][rp * 2 + 1] * inv[rp];
            size_t o = ((size_t)(b * Lq + qrow)) * Hdim + h * HD + d0;
            *(__half2*)(g_ATTf + o) = __floats2half2_rn(v0, v1);
        }
    }
}

// ---------------- residual + LayerNorm ---------------------------------------
__global__ __launch_bounds__(256) void ln_k(const float* __restrict__ X,
                                            const float* __restrict__ gamma,
                                            const float* __restrict__ beta,
                                            float* __restrict__ out)
{
    __shared__ float buf[Hdim];
    __shared__ float rs[8], rss[8], stats[2];
    const int m = blockIdx.x;
    const int tid = threadIdx.x;
    const int lane = tid & 31, wid = tid >> 5;

    float s = 0.f, ss = 0.f;
#pragma unroll
    for (int i = 0; i < 4; i++) {
        int hh = i * 256 + tid;
        float v = g_O[(size_t)m * Hdim + hh] + X[(size_t)m * Hdim + hh];
        buf[hh] = v;
        s += v; ss += v * v;
    }
#pragma unroll
    for (int o = 16; o > 0; o >>= 1) {
        s  += __shfl_xor_sync(0xffffffffu, s, o);
        ss += __shfl_xor_sync(0xffffffffu, ss, o);
    }
    if (lane == 0) { rs[wid] = s; rss[wid] = ss; }
    __syncthreads();
    if (tid == 0) {
        float S = 0.f, SS = 0.f;
#pragma unroll
        for (int i = 0; i < 8; i++) { S += rs[i]; SS += rss[i]; }
        float mu = S * (1.0f / Hdim);
        stats[0] = mu;
        stats[1] = rsqrtf(SS * (1.0f / Hdim) - mu * mu + 1e-12f);
    }
    __syncthreads();
    float mu = stats[0], r = stats[1];
#pragma unroll
    for (int i = 0; i < 4; i++) {
        int hh = i * 256 + tid;
        out[(size_t)m * Hdim + hh] = (buf[hh] - mu) * r * gamma[hh] + beta[hh];
    }
}

// ---------------- launch ------------------------------------------------------
extern "C" void kernel_launch(void* const* d_in, const int* in_sizes, int n_in,
                              void* d_out, int out_size)
{
    const float* X     = (const float*)d_in[0];
    const float* mask  = (const float*)d_in[1];
    const float* Wq    = (const float*)d_in[2];
    const float* bq    = (const float*)d_in[3];
    const float* Wk    = (const float*)d_in[4];
    const float* bk    = (const float*)d_in[5];
    const float* Wv    = (const float*)d_in[6];
    const float* bv    = (const float*)d_in[7];
    const float* Wo    = (const float*)d_in[8];
    const float* bo    = (const float*)d_in[9];
    const float* gamma = (const float*)d_in[10];
    const float* beta  = (const float*)d_in[11];

    cudaFuncSetAttribute(gemm_f16, cudaFuncAttributeMaxDynamicSharedMemorySize,
                         GEMM_SMEM_BYTES);
    cudaFuncSetAttribute(attn_k, cudaFuncAttributeMaxDynamicSharedMemorySize,
                         ATTN_SMEM_BYTES);

    split_x<<<(MROWS * Hdim) / 1024, 256>>>(X);
    split_w<<<dim3(Hdim / 32, Hdim / 32, 4), 256>>>(Wq, Wk, Wv, Wo);

    // merged QKV projections, fp16 single-plane
    gemm_f16<<<dim3(8, 32, 3), 256, GEMM_SMEM_BYTES>>>(bq, bk, bv, bo, 0);

    attn_k<<<dim3(Lq / 128, NH, Bdim), 256, ATTN_SMEM_BYTES>>>(mask);

    // O-projection, fp16 single-plane
    gemm_f16<<<dim3(8, 32, 1), 256, GEMM_SMEM_BYTES>>>(bq, bk, bv, bo, 3);

    ln_k<<<MROWS, 256>>>(X, gamma, beta, (float*)d_out);
}